// round 8
// baseline (speedup 1.0000x reference)
#include <cuda_runtime.h>
#include <math.h>

#define HI    256
#define WI    256
#define NPIX  262144
#define PPB   128
#define NTH   256

#define H2S   260     // h2 px-major stride: mod 32 = 4 -> conflict-free frags
#define H1S   68      // h1 px-major stride
#define WTS   68      // weight-tile stride (64 k + pad)
#define SDS   68      // sD staging stride
#define XCS   65      // xc stride

typedef unsigned int u32;

__device__ float g_xt[HI * WI * 64];          // x transposed [y][x][c]   16 MB
__device__ float g_dw[NPIX * 9 * 64];         // dw scratch [pix][t][c]  604 MB (L2-resident readback)

struct __align__(16) SmemA {
    float h2[PPB * H2S];                       // 133120 B
    float wt[64 * WTS];                        //  17408 B
    union { float h1[PPB * H1S]; float sD[PPB * SDS]; } u;  // 34816 B
    float xc[PPB * XCS];                       //  33280 B
    float pose[3][PPB];                        //   1536 B
    int   iy[PPB];                             //    512 B
    int   ix[PPB];                             //    512 B
    float sbias[64];                           //    256 B
    float sbias2[64];                          //    256 B
};                                             // 221696 B

__device__ __forceinline__ u32 tf32bits(float x) {
    u32 r; asm("cvt.rna.tf32.f32 %0, %1;" : "=r"(r) : "f"(x)); return r;
}
__device__ __forceinline__ float tf32f(float x) { return __uint_as_float(tf32bits(x)); }

__device__ __forceinline__ void mma_tf32(float d[4], const u32 a[4], const u32 b[2]) {
    asm volatile(
        "mma.sync.aligned.m16n8k8.row.col.f32.tf32.tf32.f32 "
        "{%0,%1,%2,%3}, {%4,%5,%6,%7}, {%8,%9}, {%0,%1,%2,%3};"
        : "+f"(d[0]), "+f"(d[1]), "+f"(d[2]), "+f"(d[3])
        : "r"(a[0]), "r"(a[1]), "r"(a[2]), "r"(a[3]), "r"(b[0]), "r"(b[1]));
}

// ======== prep: x[64][256][256] -> g_xt[y][x][64] ========
__global__ void __launch_bounds__(256)
transpose_x_kernel(const float* __restrict__ x) {
    extern __shared__ float tile[];   // [64][257]
    const int y   = blockIdx.x;
    const int tid = threadIdx.x;
    for (int i = tid; i < 64 * 256; i += 256) {
        int c = i >> 8, xx = i & 255;
        tile[c * 257 + xx] = __ldg(x + c * 65536 + y * 256 + xx);
    }
    __syncthreads();
    for (int i = tid; i < 64 * 256; i += 256) {
        int xx = i >> 6, c = i & 63;
        g_xt[(y * 256 + xx) * 64 + c] = tile[c * 257 + xx];
    }
}

// ======== warp GEMM: 32px x 32n tile, K=64 (8 x m16n8k8 tf32) ========
template<int AS>
__device__ __forceinline__ void warp_gemm8(const float* __restrict__ A,
                                           const float* __restrict__ W,
                                           float d[2][4][4],
                                           int px0, int n0, int lane, int acol0)
{
    const float* a0 = A + (px0 + (lane >> 2)) * AS + acol0 + (lane & 3);
    const float* b0 = W + (n0 + (lane >> 2)) * WTS + (lane & 3);
    #pragma unroll
    for (int ks = 0; ks < 8; ks++) {
        u32 a[2][4], b[4][2];
        #pragma unroll
        for (int mi = 0; mi < 2; mi++) {
            const float* ap = a0 + mi * 16 * AS + ks * 8;
            a[mi][0] = __float_as_uint(ap[0]);
            a[mi][1] = __float_as_uint(ap[8 * AS]);
            a[mi][2] = __float_as_uint(ap[4]);
            a[mi][3] = __float_as_uint(ap[8 * AS + 4]);
        }
        #pragma unroll
        for (int ni = 0; ni < 4; ni++) {
            const float* bp = b0 + ni * 8 * WTS + ks * 8;
            b[ni][0] = __float_as_uint(bp[0]);
            b[ni][1] = __float_as_uint(bp[4]);
        }
        #pragma unroll
        for (int mi = 0; mi < 2; mi++)
            #pragma unroll
            for (int ni = 0; ni < 4; ni++)
                mma_tf32(d[mi][ni], a[mi], b[ni]);
    }
}

// ======== layers 1+2 of one branch: pose -> h1 -> h2 ========
__device__ void layers12(SmemA& s,
                         const float* __restrict__ w1, const float* __restrict__ b1,
                         const float* __restrict__ w2, const float* __restrict__ b2,
                         int tid)
{
    const int warp = tid >> 5, lane = tid & 31;
    const int px0 = (warp & 3) * 32;
    const int n0  = (warp >> 2) * 32;

    // layer 1 (scalar)
    {
        int o = tid & 63, pb = tid >> 6;
        float wa = __ldg(w1 + o * 3 + 0);
        float wb = __ldg(w1 + o * 3 + 1);
        float wc = __ldg(w1 + o * 3 + 2);
        float bb = __ldg(b1 + o);
        #pragma unroll 4
        for (int p = pb * 32; p < pb * 32 + 32; p++) {
            float v = fmaf(wa, s.pose[0][p],
                      fmaf(wb, s.pose[1][p],
                      fmaf(wc, s.pose[2][p], bb)));
            s.u.h1[p * H1S + o] = tf32f(fmaxf(v, 0.f));
        }
    }
    __syncthreads();

    // layer 2: 4 o-chunks of 64, K=64
    for (int och = 0; och < 4; och++) {
        #pragma unroll
        for (int it = 0; it < 4; it++) {
            int idx = tid + it * 256;            // 1024 float4
            int row = idx >> 4, c4 = idx & 15;
            float4 v = __ldg((const float4*)(w2 + (och * 64 + row) * 64) + c4);
            v.x = tf32f(v.x); v.y = tf32f(v.y); v.z = tf32f(v.z); v.w = tf32f(v.w);
            *(float4*)&s.wt[row * WTS + c4 * 4] = v;
        }
        if (tid < 64) s.sbias2[tid] = __ldg(b2 + och * 64 + tid);
        __syncthreads();

        float d[2][4][4];
        #pragma unroll
        for (int mi = 0; mi < 2; mi++)
            #pragma unroll
            for (int ni = 0; ni < 4; ni++)
                #pragma unroll
                for (int j = 0; j < 4; j++) d[mi][ni][j] = 0.f;

        warp_gemm8<H1S>(s.u.h1, s.wt, d, px0, n0, lane, 0);

        #pragma unroll
        for (int mi = 0; mi < 2; mi++)
            #pragma unroll
            for (int ni = 0; ni < 4; ni++)
                #pragma unroll
                for (int j = 0; j < 4; j++) {
                    int px = px0 + mi * 16 + (lane >> 2) + ((j >> 1) << 3);
                    int ol = n0 + ni * 8 + 2 * (lane & 3) + (j & 1);
                    float v = fmaxf(d[mi][ni][j] + s.sbias2[ol], 0.f);
                    s.h2[px * H2S + och * 64 + ol] = tf32f(v);
                }
        __syncthreads();
    }
}

__global__ void __launch_bounds__(NTH, 1)
biup_fused(const float* __restrict__ poseMap,
           const int*   __restrict__ imY, const int* __restrict__ imX,
           const float* __restrict__ sigmar,
           const float* __restrict__ dw_w1, const float* __restrict__ dw_b1,
           const float* __restrict__ dw_w2, const float* __restrict__ dw_b2,
           const float* __restrict__ dw_w3, const float* __restrict__ dw_b3,
           const float* __restrict__ pw_w1, const float* __restrict__ pw_b1,
           const float* __restrict__ pw_w2, const float* __restrict__ pw_b2,
           const float* __restrict__ pw_w3, const float* __restrict__ pw_b3,
           float* __restrict__ out)
{
    extern __shared__ __align__(16) unsigned char smem_raw[];
    SmemA& s = *reinterpret_cast<SmemA*>(smem_raw);
    const int tid  = threadIdx.x;
    const int warp = tid >> 5, lane = tid & 31;
    const int px0 = (warp & 3) * 32;
    const int n0  = (warp >> 2) * 32;
    const int pix0 = blockIdx.x * PPB;

    for (int i = tid; i < 3 * PPB; i += NTH) {
        int j = i >> 7, pp = i & 127;
        s.pose[j][pp] = __ldg(poseMap + j * NPIX + pix0 + pp);
    }
    if (tid < PPB)           s.iy[tid]       = __ldg(imY + pix0 + tid);
    else if (tid < 2 * PPB)  s.ix[tid - PPB] = __ldg(imX + pix0 + tid - PPB);
    __syncthreads();

    // ===================== DW branch =====================
    layers12(s, dw_w1, dw_b1, dw_w2, dw_b2, tid);

    // layer 3: 9 tap phases, K=256 in 4 chunks of 64 -> g_dw (with bias)
    for (int p = 0; p < 9; p++) {
        if (tid < 64) s.sbias[tid] = __ldg(dw_b3 + tid * 9 + p);

        float d[2][4][4];
        #pragma unroll
        for (int mi = 0; mi < 2; mi++)
            #pragma unroll
            for (int ni = 0; ni < 4; ni++)
                #pragma unroll
                for (int j = 0; j < 4; j++) d[mi][ni][j] = 0.f;

        for (int kc = 0; kc < 4; kc++) {
            #pragma unroll
            for (int it = 0; it < 4; it++) {
                int idx = tid + it * 256;        // 1024 float4
                int row = idx >> 4, c4 = idx & 15;
                float4 v = __ldg((const float4*)(dw_w3 + (row * 9 + p) * 256 + kc * 64) + c4);
                v.x = tf32f(v.x); v.y = tf32f(v.y); v.z = tf32f(v.z); v.w = tf32f(v.w);
                *(float4*)&s.wt[row * WTS + c4 * 4] = v;
            }
            __syncthreads();
            warp_gemm8<H2S>(s.h2, s.wt, d, px0, n0, lane, kc * 64);
            __syncthreads();
        }

        // stage D (+bias) -> sD[px][c]
        #pragma unroll
        for (int mi = 0; mi < 2; mi++)
            #pragma unroll
            for (int ni = 0; ni < 4; ni++)
                #pragma unroll
                for (int j = 0; j < 4; j++) {
                    int px = px0 + mi * 16 + (lane >> 2) + ((j >> 1) << 3);
                    int c  = n0 + ni * 8 + 2 * (lane & 3) + (j & 1);
                    s.u.sD[px * SDS + c] = d[mi][ni][j] + s.sbias[c];
                }
        __syncthreads();

        // flush -> g_dw[(pix)*9 + p][c], coalesced
        #pragma unroll
        for (int it = 0; it < 8; it++) {
            int idx = tid + it * 256;            // 2048 float4
            int px = idx >> 4, c4 = idx & 15;
            float4 v = *(const float4*)&s.u.sD[px * SDS + c4 * 4];
            *((float4*)(g_dw + ((pix0 + px) * 9 + p) * 64) + c4) = v;
        }
        __syncthreads();
    }

    // ===================== tail: gather + double softmax -> xc ====================
    {
        const int c   = tid & 63;
        const int pxg = tid >> 6;                // 0..3
        const float sg = __ldg(sigmar + c);
        #pragma unroll 1
        for (int it = 0; it < 32; it++) {
            const int px  = pxg * 32 + it;
            const int pix = pix0 + px;
            const int iy = s.iy[px], ix = s.ix[px];

            float dwv[9], h[9];
            #pragma unroll
            for (int t = 0; t < 9; t++)
                dwv[t] = __ldg(g_dw + (pix * 9 + t) * 64 + c);
            #pragma unroll
            for (int t = 0; t < 9; t++) {
                int yy = iy + t / 3 - 1;
                int xx = ix + t % 3 - 1;
                bool ok = ((unsigned)yy < HI) && ((unsigned)xx < WI);
                h[t] = ok ? __ldg(&g_xt[(yy * WI + xx) * 64 + c]) : 0.f;
            }

            float m = dwv[0];
            #pragma unroll
            for (int t = 1; t < 9; t++) m = fmaxf(m, dwv[t]);
            float es = 0.f, hm = 0.f;
            #pragma unroll
            for (int t = 0; t < 9; t++) {
                float e = __expf(dwv[t] - m);
                es += e;
                hm  = fmaf(h[t], e, hm);
            }
            float mean = hm / es;

            float bw[9], m2 = -3.4e38f;
            #pragma unroll
            for (int t = 0; t < 9; t++) {
                float dd = h[t] - mean;
                bw[t] = fmaf(sg * dd, dd, dwv[t]);
                m2 = fmaxf(m2, bw[t]);
            }
            float s2 = 0.f, xcv = 0.f;
            #pragma unroll
            for (int t = 0; t < 9; t++) {
                float ee = __expf(bw[t] - m2);
                s2  += ee;
                xcv  = fmaf(h[t], ee, xcv);
            }
            s.xc[px * XCS + c] = xcv / s2;
        }
    }
    __syncthreads();

    // ===================== PW branch =====================
    layers12(s, pw_w1, pw_b1, pw_w2, pw_b2, tid);

    // layer 3: 3 phases; contract with xc in-block, write out directly
    for (int p = 0; p < 3; p++) {
        if (tid < 64) s.sbias[tid] = __ldg(pw_b3 + tid * 3 + p);

        float d[2][4][4];
        #pragma unroll
        for (int mi = 0; mi < 2; mi++)
            #pragma unroll
            for (int ni = 0; ni < 4; ni++)
                #pragma unroll
                for (int j = 0; j < 4; j++) d[mi][ni][j] = 0.f;

        for (int kc = 0; kc < 4; kc++) {
            #pragma unroll
            for (int it = 0; it < 4; it++) {
                int idx = tid + it * 256;
                int row = idx >> 4, c4 = idx & 15;
                float4 v = __ldg((const float4*)(pw_w3 + (row * 3 + p) * 256 + kc * 64) + c4);
                v.x = tf32f(v.x); v.y = tf32f(v.y); v.z = tf32f(v.z); v.w = tf32f(v.w);
                *(float4*)&s.wt[row * WTS + c4 * 4] = v;
            }
            __syncthreads();
            warp_gemm8<H2S>(s.h2, s.wt, d, px0, n0, lane, kc * 64);
            __syncthreads();
        }

        // stage D (+bias)
        #pragma unroll
        for (int mi = 0; mi < 2; mi++)
            #pragma unroll
            for (int ni = 0; ni < 4; ni++)
                #pragma unroll
                for (int j = 0; j < 4; j++) {
                    int px = px0 + mi * 16 + (lane >> 2) + ((j >> 1) << 3);
                    int c  = n0 + ni * 8 + 2 * (lane & 3) + (j & 1);
                    s.u.sD[px * SDS + c] = d[mi][ni][j] + s.sbias[c];
                }
        __syncthreads();

        // contract: out[p][pix0+px] = sum_c xc[px][c] * sD[px][c]
        {
            const int px2  = tid >> 1;           // 0..127
            const int half = tid & 1;
            const float* row = &s.u.sD[px2 * SDS + half * 32];
            const float* xr  = &s.xc[px2 * XCS + half * 32];
            float acc = 0.f;
            #pragma unroll
            for (int cc = 0; cc < 32; cc++)
                acc = fmaf(row[cc], xr[cc], acc);
            acc += __shfl_xor_sync(0xffffffffu, acc, 1);
            if (half == 0)
                out[p * NPIX + pix0 + px2] = acc;
        }
        __syncthreads();
    }
}

extern "C" void kernel_launch(void* const* d_in, const int* in_sizes, int n_in,
                              void* d_out, int out_size) {
    (void)in_sizes; (void)n_in; (void)out_size;
    const float* x      = (const float*)d_in[0];
    const float* pose   = (const float*)d_in[1];
    const int*   imY    = (const int*)  d_in[2];
    const int*   imX    = (const int*)  d_in[3];
    const float* sigmar = (const float*)d_in[4];
    const float* dw_w1  = (const float*)d_in[5];
    const float* dw_b1  = (const float*)d_in[6];
    const float* dw_w2  = (const float*)d_in[7];
    const float* dw_b2  = (const float*)d_in[8];
    const float* dw_w3  = (const float*)d_in[9];
    const float* dw_b3  = (const float*)d_in[10];
    const float* pw_w1  = (const float*)d_in[11];
    const float* pw_b1  = (const float*)d_in[12];
    const float* pw_w2  = (const float*)d_in[13];
    const float* pw_b2  = (const float*)d_in[14];
    const float* pw_w3  = (const float*)d_in[15];
    const float* pw_b3  = (const float*)d_in[16];
    float* out = (float*)d_out;

    const int tsmem = 64 * 257 * 4;
    cudaFuncSetAttribute(transpose_x_kernel,
                         cudaFuncAttributeMaxDynamicSharedMemorySize, tsmem);
    transpose_x_kernel<<<256, 256, tsmem>>>(x);

    const int asmem = (int)sizeof(SmemA);
    cudaFuncSetAttribute(biup_fused,
                         cudaFuncAttributeMaxDynamicSharedMemorySize, asmem);
    biup_fused<<<NPIX / PPB, NTH, asmem>>>(
        pose, imY, imX, sigmar,
        dw_w1, dw_b1, dw_w2, dw_b2, dw_w3, dw_b3,
        pw_w1, pw_b1, pw_w2, pw_b2, pw_w3, pw_b3,
        out);
}

// round 10
// speedup vs baseline: 1.0200x; 1.0200x over previous
#include <cuda_runtime.h>
#include <math.h>

#define HI    256
#define WI    256
#define NPIX  262144
#define PPB   128
#define NTH   512

#define H2S   260     // h2 px-major stride: mod 32 = 4 -> conflict-free frags
#define H1S   68      // h1 px-major stride
#define WTS   68      // weight-tile stride (64 k + pad)
#define SDS   68      // sD staging stride
#define XCS   65      // xc stride

typedef unsigned int u32;

__device__ float g_xt[HI * WI * 64];          // x transposed [y][x][c]   16 MB
__device__ float g_dw[NPIX * 9 * 64];         // dw scratch [pix][t][c]  (block-local readback)

struct __align__(16) SmemA {
    float h2[PPB * H2S];                       // 133120 B
    float wt[64 * WTS];                        //  17408 B
    union { float h1[PPB * H1S]; float sD[PPB * SDS]; } u;  // 34816 B
    float xc[PPB * XCS];                       //  33280 B
    float pose[3][PPB];                        //   1536 B
    int   iy[PPB];                             //    512 B
    int   ix[PPB];                             //    512 B
    float sbias[64];                           //    256 B
    float sbias2[64];                          //    256 B
};                                             // 221696 B

__device__ __forceinline__ u32 tf32bits(float x) {
    u32 r; asm("cvt.rna.tf32.f32 %0, %1;" : "=r"(r) : "f"(x)); return r;
}
__device__ __forceinline__ float tf32f(float x) { return __uint_as_float(tf32bits(x)); }

__device__ __forceinline__ void mma_tf32(float d[4], const u32 a[4], const u32 b[2]) {
    asm volatile(
        "mma.sync.aligned.m16n8k8.row.col.f32.tf32.tf32.f32 "
        "{%0,%1,%2,%3}, {%4,%5,%6,%7}, {%8,%9}, {%0,%1,%2,%3};"
        : "+f"(d[0]), "+f"(d[1]), "+f"(d[2]), "+f"(d[3])
        : "r"(a[0]), "r"(a[1]), "r"(a[2]), "r"(a[3]), "r"(b[0]), "r"(b[1]));
}

// ======== prep: x[64][256][256] -> g_xt[y][x][64] ========
__global__ void __launch_bounds__(256)
transpose_x_kernel(const float* __restrict__ x) {
    extern __shared__ float tile[];   // [64][257]
    const int y   = blockIdx.x;
    const int tid = threadIdx.x;
    for (int i = tid; i < 64 * 256; i += 256) {
        int c = i >> 8, xx = i & 255;
        tile[c * 257 + xx] = __ldg(x + c * 65536 + y * 256 + xx);
    }
    __syncthreads();
    for (int i = tid; i < 64 * 256; i += 256) {
        int xx = i >> 6, c = i & 63;
        g_xt[(y * 256 + xx) * 64 + c] = tile[c * 257 + xx];
    }
}

// ======== weight-chunk prefetch (regs) + commit (smem, tf32-rounded) ========
// chunk = 64 rows x 64 k; each of 512 threads owns 2 float4
__device__ __forceinline__ void pf_w(const float* __restrict__ base, int rs,
                                     int tid, float4 r[2]) {
    #pragma unroll
    for (int it = 0; it < 2; it++) {
        int idx = tid + it * NTH;
        int row = idx >> 4, c4 = idx & 15;
        r[it] = __ldg((const float4*)(base + row * rs) + c4);
    }
}
__device__ __forceinline__ void sts_w(float* __restrict__ wt, int tid, const float4 r[2]) {
    #pragma unroll
    for (int it = 0; it < 2; it++) {
        int idx = tid + it * NTH;
        int row = idx >> 4, c4 = idx & 15;
        float4 v = r[it];
        v.x = tf32f(v.x); v.y = tf32f(v.y); v.z = tf32f(v.z); v.w = tf32f(v.w);
        *(float4*)&wt[row * WTS + c4 * 4] = v;
    }
}

// ======== warp GEMM: 32px x 16n tile, K=64 (8 x m16n8k8 tf32) ========
template<int AS>
__device__ __forceinline__ void warp_gemm8(const float* __restrict__ A,
                                           const float* __restrict__ W,
                                           float d[2][2][4],
                                           int px0, int n0, int lane, int acol0)
{
    const float* a0 = A + (px0 + (lane >> 2)) * AS + acol0 + (lane & 3);
    const float* b0 = W + (n0 + (lane >> 2)) * WTS + (lane & 3);
    #pragma unroll
    for (int ks = 0; ks < 8; ks++) {
        u32 a[2][4], b[2][2];
        #pragma unroll
        for (int mi = 0; mi < 2; mi++) {
            const float* ap = a0 + mi * 16 * AS + ks * 8;
            a[mi][0] = __float_as_uint(ap[0]);
            a[mi][1] = __float_as_uint(ap[8 * AS]);
            a[mi][2] = __float_as_uint(ap[4]);
            a[mi][3] = __float_as_uint(ap[8 * AS + 4]);
        }
        #pragma unroll
        for (int ni = 0; ni < 2; ni++) {
            const float* bp = b0 + ni * 8 * WTS + ks * 8;
            b[ni][0] = __float_as_uint(bp[0]);
            b[ni][1] = __float_as_uint(bp[4]);
        }
        #pragma unroll
        for (int mi = 0; mi < 2; mi++)
            #pragma unroll
            for (int ni = 0; ni < 2; ni++)
                mma_tf32(d[mi][ni], a[mi], b[ni]);
    }
}

// ======== layers 1+2 of one branch (pfr must hold w2 chunk och0 on entry;
//          on exit pfr holds the caller-requested nextw chunk) ========
__device__ void layers12(SmemA& s,
                         const float* __restrict__ w1, const float* __restrict__ b1,
                         const float* __restrict__ w2, const float* __restrict__ b2,
                         int tid, float4 pfr[2],
                         const float* __restrict__ nextw, int nextrs)
{
    const int warp = tid >> 5, lane = tid & 31;
    const int px0 = (warp & 3) * 32;
    const int n0  = (warp >> 2) * 16;

    // layer 1 (scalar)
    {
        int o = tid & 63, pb = tid >> 6;       // 8 groups of 16 px
        float wa = __ldg(w1 + o * 3 + 0);
        float wb = __ldg(w1 + o * 3 + 1);
        float wc = __ldg(w1 + o * 3 + 2);
        float bb = __ldg(b1 + o);
        #pragma unroll 4
        for (int p = pb * 16; p < pb * 16 + 16; p++) {
            float v = fmaf(wa, s.pose[0][p],
                      fmaf(wb, s.pose[1][p],
                      fmaf(wc, s.pose[2][p], bb)));
            s.u.h1[p * H1S + o] = tf32f(fmaxf(v, 0.f));
        }
    }

    // layer 2: 4 o-chunks of 64, K=64
    for (int och = 0; och < 4; och++) {
        __syncthreads();                        // h1 ready / wt free
        sts_w(s.wt, tid, pfr);
        if (och < 3)      pf_w(w2 + (och + 1) * 4096, 64, tid, pfr);
        else if (nextw)   pf_w(nextw, nextrs, tid, pfr);
        if (tid < 64) s.sbias2[tid] = __ldg(b2 + och * 64 + tid);
        __syncthreads();

        float d[2][2][4];
        #pragma unroll
        for (int mi = 0; mi < 2; mi++)
            #pragma unroll
            for (int ni = 0; ni < 2; ni++)
                #pragma unroll
                for (int j = 0; j < 4; j++) d[mi][ni][j] = 0.f;

        warp_gemm8<H1S>(s.u.h1, s.wt, d, px0, n0, lane, 0);

        #pragma unroll
        for (int mi = 0; mi < 2; mi++)
            #pragma unroll
            for (int ni = 0; ni < 2; ni++)
                #pragma unroll
                for (int j = 0; j < 4; j++) {
                    int px = px0 + mi * 16 + (lane >> 2) + ((j >> 1) << 3);
                    int ol = n0 + ni * 8 + 2 * (lane & 3) + (j & 1);
                    float v = fmaxf(d[mi][ni][j] + s.sbias2[ol], 0.f);
                    s.h2[px * H2S + och * 64 + ol] = tf32f(v);
                }
    }
}

__global__ void __launch_bounds__(NTH, 1)
biup_fused(const float* __restrict__ poseMap,
           const int*   __restrict__ imY, const int* __restrict__ imX,
           const float* __restrict__ sigmar,
           const float* __restrict__ dw_w1, const float* __restrict__ dw_b1,
           const float* __restrict__ dw_w2, const float* __restrict__ dw_b2,
           const float* __restrict__ dw_w3, const float* __restrict__ dw_b3,
           const float* __restrict__ pw_w1, const float* __restrict__ pw_b1,
           const float* __restrict__ pw_w2, const float* __restrict__ pw_b2,
           const float* __restrict__ pw_w3, const float* __restrict__ pw_b3,
           float* __restrict__ out)
{
    extern __shared__ __align__(16) unsigned char smem_raw[];
    SmemA& s = *reinterpret_cast<SmemA*>(smem_raw);
    const int tid  = threadIdx.x;
    const int warp = tid >> 5, lane = tid & 31;
    const int px0 = (warp & 3) * 32;
    const int n0  = (warp >> 2) * 16;
    const int pix0 = blockIdx.x * PPB;

    float4 pfr[2];
    pf_w(dw_w2, 64, tid, pfr);                  // first chunk in the chain

    if (tid < 3 * PPB) {
        int j = tid >> 7, pp = tid & 127;
        s.pose[j][pp] = __ldg(poseMap + j * NPIX + pix0 + pp);
    }
    if (tid < PPB)           s.iy[tid]       = __ldg(imY + pix0 + tid);
    else if (tid < 2 * PPB)  s.ix[tid - PPB] = __ldg(imX + pix0 + tid - PPB);
    __syncthreads();

    // ===================== DW branch =====================
    layers12(s, dw_w1, dw_b1, dw_w2, dw_b2, tid, pfr, dw_w3, 9 * 256);

    // layer 3: 9 tap phases, K=256 in 4 chunks of 64 -> g_dw (with bias)
    float d[2][2][4];
    for (int p = 0; p < 9; p++) {
        for (int kc = 0; kc < 4; kc++) {
            __syncthreads();                    // prior gemm done with wt
            sts_w(s.wt, tid, pfr);
            if (kc < 3)       pf_w(dw_w3 + p * 256 + (kc + 1) * 64, 9 * 256, tid, pfr);
            else if (p < 8)   pf_w(dw_w3 + (p + 1) * 256, 9 * 256, tid, pfr);
            else              pf_w(pw_w2, 64, tid, pfr);    // chain into PW branch
            if (kc == 0 && tid < 64) s.sbias[tid] = __ldg(dw_b3 + tid * 9 + p);
            __syncthreads();

            if (kc == 0) {
                #pragma unroll
                for (int mi = 0; mi < 2; mi++)
                    #pragma unroll
                    for (int ni = 0; ni < 2; ni++)
                        #pragma unroll
                        for (int j = 0; j < 4; j++) d[mi][ni][j] = 0.f;
            }
            warp_gemm8<H2S>(s.h2, s.wt, d, px0, n0, lane, kc * 64);
        }

        // stage D (+bias) -> sD[px][c]
        #pragma unroll
        for (int mi = 0; mi < 2; mi++)
            #pragma unroll
            for (int ni = 0; ni < 2; ni++)
                #pragma unroll
                for (int j = 0; j < 4; j++) {
                    int px = px0 + mi * 16 + (lane >> 2) + ((j >> 1) << 3);
                    int c  = n0 + ni * 8 + 2 * (lane & 3) + (j & 1);
                    s.u.sD[px * SDS + c] = d[mi][ni][j] + s.sbias[c];
                }
        __syncthreads();

        // flush -> g_dw[(pix)*9 + p][c], coalesced
        #pragma unroll
        for (int it = 0; it < 4; it++) {
            int idx = tid + it * NTH;           // 2048 float4
            int px = idx >> 4, c4 = idx & 15;
            float4 v = *(const float4*)&s.u.sD[px * SDS + c4 * 4];
            *((float4*)(g_dw + ((pix0 + px) * 9 + p) * 64) + c4) = v;
        }
        // next phase's chunk-top __syncthreads orders flush vs sD reuse
    }
    __syncthreads();                            // g_dw of this block fully written

    // ===================== tail: gather + double softmax -> xc ====================
    {
        const int c   = tid & 63;
        const int pxg = tid >> 6;               // 0..7
        const float sg = __ldg(sigmar + c);
        #pragma unroll 1
        for (int it = 0; it < 16; it++) {
            const int px  = pxg * 16 + it;
            const int pix = pix0 + px;
            const int iy = s.iy[px], ix = s.ix[px];

            float dwv[9], h[9];
            #pragma unroll
            for (int t = 0; t < 9; t++)
                dwv[t] = __ldg(g_dw + (pix * 9 + t) * 64 + c);
            #pragma unroll
            for (int t = 0; t < 9; t++) {
                int yy = iy + t / 3 - 1;
                int xx = ix + t % 3 - 1;
                bool ok = ((unsigned)yy < HI) && ((unsigned)xx < WI);
                h[t] = ok ? __ldg(&g_xt[(yy * WI + xx) * 64 + c]) : 0.f;
            }

            float m = dwv[0];
            #pragma unroll
            for (int t = 1; t < 9; t++) m = fmaxf(m, dwv[t]);
            float es = 0.f, hm = 0.f;
            #pragma unroll
            for (int t = 0; t < 9; t++) {
                float e = __expf(dwv[t] - m);
                es += e;
                hm  = fmaf(h[t], e, hm);
            }
            float mean = hm / es;

            float bw[9], m2 = -3.4e38f;
            #pragma unroll
            for (int t = 0; t < 9; t++) {
                float dd = h[t] - mean;
                bw[t] = fmaf(sg * dd, dd, dwv[t]);
                m2 = fmaxf(m2, bw[t]);
            }
            float s2 = 0.f, xcv = 0.f;
            #pragma unroll
            for (int t = 0; t < 9; t++) {
                float ee = __expf(bw[t] - m2);
                s2  += ee;
                xcv  = fmaf(h[t], ee, xcv);
            }
            s.xc[px * XCS + c] = xcv / s2;
        }
    }
    __syncthreads();

    // ===================== PW branch (pfr already holds pw_w2 och0) ============
    layers12(s, pw_w1, pw_b1, pw_w2, pw_b2, tid, pfr, pw_w3, 3 * 256);

    // layer 3: 3 phases; contract with xc in-block, write out directly
    for (int p = 0; p < 3; p++) {
        for (int kc = 0; kc < 4; kc++) {
            __syncthreads();
            sts_w(s.wt, tid, pfr);
            if (kc < 3)       pf_w(pw_w3 + p * 256 + (kc + 1) * 64, 3 * 256, tid, pfr);
            else if (p < 2)   pf_w(pw_w3 + (p + 1) * 256, 3 * 256, tid, pfr);
            if (kc == 0 && tid < 64) s.sbias[tid] = __ldg(pw_b3 + tid * 3 + p);
            __syncthreads();

            if (kc == 0) {
                #pragma unroll
                for (int mi = 0; mi < 2; mi++)
                    #pragma unroll
                    for (int ni = 0; ni < 2; ni++)
                        #pragma unroll
                        for (int j = 0; j < 4; j++) d[mi][ni][j] = 0.f;
            }
            warp_gemm8<H2S>(s.h2, s.wt, d, px0, n0, lane, kc * 64);
        }

        // stage D (+bias)
        #pragma unroll
        for (int mi = 0; mi < 2; mi++)
            #pragma unroll
            for (int ni = 0; ni < 2; ni++)
                #pragma unroll
                for (int j = 0; j < 4; j++) {
                    int px = px0 + mi * 16 + (lane >> 2) + ((j >> 1) << 3);
                    int c  = n0 + ni * 8 + 2 * (lane & 3) + (j & 1);
                    s.u.sD[px * SDS + c] = d[mi][ni][j] + s.sbias[c];
                }
        __syncthreads();

        // contract: out[p][pix0+px] = sum_c xc[px][c] * sD[px][c]
        {
            const int px2 = tid >> 2;            // 0..127
            const int q   = tid & 3;
            const float* row = &s.u.sD[px2 * SDS + q * 16];
            const float* xr  = &s.xc[px2 * XCS + q * 16];
            float acc = 0.f;
            #pragma unroll
            for (int cc = 0; cc < 16; cc++)
                acc = fmaf(row[cc], xr[cc], acc);
            acc += __shfl_xor_sync(0xffffffffu, acc, 1);
            acc += __shfl_xor_sync(0xffffffffu, acc, 2);
            if (q == 0)
                out[p * NPIX + pix0 + px2] = acc;
        }
        // next phase's chunk-top sync orders contraction vs sD reuse
    }
}

extern "C" void kernel_launch(void* const* d_in, const int* in_sizes, int n_in,
                              void* d_out, int out_size) {
    (void)in_sizes; (void)n_in; (void)out_size;
    const float* x      = (const float*)d_in[0];
    const float* pose   = (const float*)d_in[1];
    const int*   imY    = (const int*)  d_in[2];
    const int*   imX    = (const int*)  d_in[3];
    const float* sigmar = (const float*)d_in[4];
    const float* dw_w1  = (const float*)d_in[5];
    const float* dw_b1  = (const float*)d_in[6];
    const float* dw_w2  = (const float*)d_in[7];
    const float* dw_b2  = (const float*)d_in[8];
    const float* dw_w3  = (const float*)d_in[9];
    const float* dw_b3  = (const float*)d_in[10];
    const float* pw_w1  = (const float*)d_in[11];
    const float* pw_b1  = (const float*)d_in[12];
    const float* pw_w2  = (const float*)d_in[13];
    const float* pw_b2  = (const float*)d_in[14];
    const float* pw_w3  = (const float*)d_in[15];
    const float* pw_b3  = (const float*)d_in[16];
    float* out = (float*)d_out;

    const int tsmem = 64 * 257 * 4;
    cudaFuncSetAttribute(transpose_x_kernel,
                         cudaFuncAttributeMaxDynamicSharedMemorySize, tsmem);
    transpose_x_kernel<<<256, 256, tsmem>>>(x);

    const int asmem = (int)sizeof(SmemA);
    cudaFuncSetAttribute(biup_fused,
                         cudaFuncAttributeMaxDynamicSharedMemorySize, asmem);
    biup_fused<<<NPIX / PPB, NTH, asmem>>>(
        pose, imY, imX, sigmar,
        dw_w1, dw_b1, dw_w2, dw_b2, dw_w3, dw_b3,
        pw_w1, pw_b1, pw_w2, pw_b2, pw_w3, pw_b3,
        out);
}

// round 12
// speedup vs baseline: 1.7593x; 1.7248x over previous
#include <cuda_runtime.h>
#include <cuda_fp16.h>
#include <math.h>

#define HI    256
#define WI    256
#define NPIX  262144
#define PPB   128
#define NTH   512

#define H2SH  264     // h2 fp16 stride: 528B = 132 words, %32=4 -> conflict-free frags
#define H1SH  72      // h1 fp16 stride: 144B = 36 words, %32=4
#define WTSH  136     // weight tile fp16 stride: 272B = 68 words, %32=4; 16B-aligned rows
#define SDS   68      // sD f32 staging stride
#define XCS   65      // xc f32 stride

typedef unsigned int u32;

__device__ float  g_xt[HI * WI * 64];     // x transposed [y][x][c]
__device__ float  g_dw[NPIX * 9 * 64];    // dw scratch [pix][t][c] (block-local readback)
__device__ __half g_dw2h[256 * 64];
__device__ __half g_dw3h[576 * 256];
__device__ __half g_pw2h[256 * 64];
__device__ __half g_pw3h[192 * 256];

struct __align__(16) SmemA {
    __half h2[PPB * H2SH];                     // 67584 B
    __half wt[64 * WTSH];                      // 17408 B
    union { __half h1[PPB * H1SH]; float sD[PPB * SDS]; } u;  // 34816 B
    float xc[PPB * XCS];                       // 33280 B
    float pose[3][PPB];                        //  1536 B
    int   iy[PPB];                             //   512 B
    int   ix[PPB];                             //   512 B
    float sbias[64];                           //   256 B
    float sbias2[64];                          //   256 B
};                                             // ~156 KB

static __device__ __forceinline__ u32 ph2(float a, float b) {
    __half2 h = __floats2half2_rn(a, b);
    return *reinterpret_cast<u32*>(&h);
}

static __device__ __forceinline__ void mma_f16(float d[4], const u32 a[4], const u32 b[2]) {
    asm volatile(
        "mma.sync.aligned.m16n8k16.row.col.f32.f16.f16.f32 "
        "{%0,%1,%2,%3}, {%4,%5,%6,%7}, {%8,%9}, {%0,%1,%2,%3};"
        : "+f"(d[0]), "+f"(d[1]), "+f"(d[2]), "+f"(d[3])
        : "r"(a[0]), "r"(a[1]), "r"(a[2]), "r"(a[3]), "r"(b[0]), "r"(b[1]));
}

// ======== prep 1: x[64][256][256] -> g_xt[y][x][64] ========
__global__ void __launch_bounds__(256)
transpose_x_kernel(const float* __restrict__ x) {
    extern __shared__ float tile[];   // [64][257]
    const int y   = blockIdx.x;
    const int tid = threadIdx.x;
    for (int i = tid; i < 64 * 256; i += 256) {
        int c = i >> 8, xx = i & 255;
        tile[c * 257 + xx] = __ldg(x + c * 65536 + y * 256 + xx);
    }
    __syncthreads();
    for (int i = tid; i < 64 * 256; i += 256) {
        int xx = i >> 6, c = i & 63;
        g_xt[(y * 256 + xx) * 64 + c] = tile[c * 257 + xx];
    }
}

// ======== prep 2: weights -> fp16 ========
__global__ void __launch_bounds__(256)
conv_weights_kernel(const float* __restrict__ dw2, const float* __restrict__ dw3,
                    const float* __restrict__ pw2, const float* __restrict__ pw3) {
    int i = blockIdx.x * blockDim.x + threadIdx.x;
    int n = gridDim.x * blockDim.x;
    for (int k = i; k < 256 * 64; k += n) g_dw2h[k] = __float2half_rn(__ldg(dw2 + k));
    for (int k = i; k < 576 * 256; k += n) g_dw3h[k] = __float2half_rn(__ldg(dw3 + k));
    for (int k = i; k < 256 * 64; k += n) g_pw2h[k] = __float2half_rn(__ldg(pw2 + k));
    for (int k = i; k < 192 * 256; k += n) g_pw3h[k] = __float2half_rn(__ldg(pw3 + k));
}

// ======== weight prefetch/commit: 8KB (pf2) and 16KB (pf3) fp16 chunks ========
static __device__ __forceinline__ void pf2(const __half* __restrict__ base,
                                           int tid, uint4 r[2]) {
    r[0] = __ldg((const uint4*)(base + (tid >> 3) * 64) + (tid & 7));
}
static __device__ __forceinline__ void sts2(__half* __restrict__ wt, int tid,
                                            const uint4 r[2]) {
    *(uint4*)&wt[(tid >> 3) * WTSH + (tid & 7) * 8] = r[0];
}
static __device__ __forceinline__ void pf3(const __half* __restrict__ base, int rs,
                                           int tid, uint4 r[2]) {
    #pragma unroll
    for (int it = 0; it < 2; it++) {
        int idx = tid + it * NTH;
        r[it] = __ldg((const uint4*)(base + (idx >> 4) * rs) + (idx & 15));
    }
}
static __device__ __forceinline__ void sts3(__half* __restrict__ wt, int tid,
                                            const uint4 r[2]) {
    #pragma unroll
    for (int it = 0; it < 2; it++) {
        int idx = tid + it * NTH;
        *(uint4*)&wt[(idx >> 4) * WTSH + (idx & 15) * 8] = r[it];
    }
}

// ======== warp GEMM: 32px x 16n, fp16 m16n8k16 ========
template<int ASH, int NKS>
static __device__ __forceinline__ void warp_gemm_h(const __half* __restrict__ A,
                                                   const __half* __restrict__ W,
                                                   float d[2][2][4],
                                                   int px0, int n0, int lane, int acol0)
{
    const __half* a0p = A + (px0 + (lane >> 2)) * ASH + acol0 + (lane & 3) * 2;
    const __half* b0p = W + (n0 + (lane >> 2)) * WTSH + (lane & 3) * 2;
    #pragma unroll
    for (int ks = 0; ks < NKS; ks++) {
        u32 a[2][4], b[2][2];
        #pragma unroll
        for (int mi = 0; mi < 2; mi++) {
            const __half* ap = a0p + mi * 16 * ASH + ks * 16;
            a[mi][0] = *(const u32*)(ap);
            a[mi][1] = *(const u32*)(ap + 8 * ASH);
            a[mi][2] = *(const u32*)(ap + 8);
            a[mi][3] = *(const u32*)(ap + 8 * ASH + 8);
        }
        #pragma unroll
        for (int ni = 0; ni < 2; ni++) {
            const __half* bp = b0p + ni * 8 * WTSH + ks * 16;
            b[ni][0] = *(const u32*)(bp);
            b[ni][1] = *(const u32*)(bp + 8);
        }
        #pragma unroll
        for (int mi = 0; mi < 2; mi++)
            #pragma unroll
            for (int ni = 0; ni < 2; ni++)
                mma_f16(d[mi][ni], a[mi], b[ni]);
    }
}

// ======== layers 1+2 of one branch; pfr holds w2h och0 on entry,
//          holds first chunk of nextw (pf3) on exit ========
static __device__ void layers12(SmemA& s,
                                const float* __restrict__ w1, const float* __restrict__ b1,
                                const __half* __restrict__ w2h, const float* __restrict__ b2,
                                int tid, uint4 pfr[2],
                                const __half* __restrict__ nextw, int nextrs)
{
    const int warp = tid >> 5, lane = tid & 31;
    const int px0 = (warp & 3) * 32;
    const int n0  = (warp >> 2) * 16;

    // layer 1 (scalar) -> h1 fp16
    {
        int o = tid & 63, pb = tid >> 6;       // 8 groups of 16 px
        float wa = __ldg(w1 + o * 3 + 0);
        float wb = __ldg(w1 + o * 3 + 1);
        float wc = __ldg(w1 + o * 3 + 2);
        float bb = __ldg(b1 + o);
        #pragma unroll 4
        for (int p = pb * 16; p < pb * 16 + 16; p++) {
            float v = fmaf(wa, s.pose[0][p],
                      fmaf(wb, s.pose[1][p],
                      fmaf(wc, s.pose[2][p], bb)));
            s.u.h1[p * H1SH + o] = __float2half_rn(fmaxf(v, 0.f));
        }
    }

    // layer 2: 4 o-chunks of 64, K=64
    for (int och = 0; och < 4; och++) {
        __syncthreads();                        // h1 ready / wt free
        sts2(s.wt, tid, pfr);
        if (och < 3) pf2(w2h + (och + 1) * 4096, tid, pfr);
        else         pf3(nextw, nextrs, tid, pfr);
        if (tid < 64) s.sbias2[tid] = __ldg(b2 + och * 64 + tid);
        __syncthreads();

        float d[2][2][4];
        #pragma unroll
        for (int mi = 0; mi < 2; mi++)
            #pragma unroll
            for (int ni = 0; ni < 2; ni++)
                #pragma unroll
                for (int j = 0; j < 4; j++) d[mi][ni][j] = 0.f;

        warp_gemm_h<H1SH, 4>(s.u.h1, s.wt, d, px0, n0, lane, 0);

        #pragma unroll
        for (int mi = 0; mi < 2; mi++)
            #pragma unroll
            for (int ni = 0; ni < 2; ni++) {
                int px  = px0 + mi * 16 + (lane >> 2);
                int olb = n0 + ni * 8 + 2 * (lane & 3);
                float b0v = s.sbias2[olb], b1v = s.sbias2[olb + 1];
                u32 v01 = ph2(fmaxf(d[mi][ni][0] + b0v, 0.f),
                              fmaxf(d[mi][ni][1] + b1v, 0.f));
                *(u32*)&s.h2[px * H2SH + och * 64 + olb] = v01;
                u32 v23 = ph2(fmaxf(d[mi][ni][2] + b0v, 0.f),
                              fmaxf(d[mi][ni][3] + b1v, 0.f));
                *(u32*)&s.h2[(px + 8) * H2SH + och * 64 + olb] = v23;
            }
    }
}

__global__ void __launch_bounds__(NTH, 1)
biup_fused(const float* __restrict__ poseMap,
           const int*   __restrict__ imY, const int* __restrict__ imX,
           const float* __restrict__ sigmar,
           const float* __restrict__ dw_w1, const float* __restrict__ dw_b1,
           const float* __restrict__ dw_b2, const float* __restrict__ dw_b3,
           const float* __restrict__ pw_w1, const float* __restrict__ pw_b1,
           const float* __restrict__ pw_b2, const float* __restrict__ pw_b3,
           float* __restrict__ out)
{
    extern __shared__ __align__(16) unsigned char smem_raw[];
    SmemA& s = *reinterpret_cast<SmemA*>(smem_raw);
    const int tid  = threadIdx.x;
    const int warp = tid >> 5, lane = tid & 31;
    const int px0 = (warp & 3) * 32;
    const int n0  = (warp >> 2) * 16;
    const int pix0 = blockIdx.x * PPB;

    uint4 pfr[2];
    pf2(g_dw2h, tid, pfr);                      // chain head (covered by layer-1 work)

    if (tid < 3 * PPB) {
        int j = tid >> 7, pp = tid & 127;
        s.pose[j][pp] = __ldg(poseMap + j * NPIX + pix0 + pp);
    }
    if (tid < PPB)           s.iy[tid]       = __ldg(imY + pix0 + tid);
    else if (tid < 2 * PPB)  s.ix[tid - PPB] = __ldg(imX + pix0 + tid - PPB);
    __syncthreads();

    // ===================== DW branch =====================
    layers12(s, dw_w1, dw_b1, g_dw2h, dw_b2, tid, pfr, g_dw3h, 9 * 256);

    // layer 3: 9 tap phases, K=256 in 2 chunks of 128 -> g_dw (with bias)
    float d[2][2][4];
    for (int p = 0; p < 9; p++) {
        for (int kc = 0; kc < 2; kc++) {
            __syncthreads();                    // prior gemm done with wt
            sts3(s.wt, tid, pfr);
            if (kc == 0)    pf3(g_dw3h + p * 256 + 128, 9 * 256, tid, pfr);
            else if (p < 8) pf3(g_dw3h + (p + 1) * 256, 9 * 256, tid, pfr);
            else            pf2(g_pw2h, tid, pfr);          // chain into PW branch
            if (kc == 0 && tid < 64) s.sbias[tid] = __ldg(dw_b3 + tid * 9 + p);
            __syncthreads();

            if (kc == 0) {
                #pragma unroll
                for (int mi = 0; mi < 2; mi++)
                    #pragma unroll
                    for (int ni = 0; ni < 2; ni++)
                        #pragma unroll
                        for (int j = 0; j < 4; j++) d[mi][ni][j] = 0.f;
            }
            warp_gemm_h<H2SH, 8>(s.h2, s.wt, d, px0, n0, lane, kc * 128);
        }

        // stage D (+bias) -> sD[px][c]
        #pragma unroll
        for (int mi = 0; mi < 2; mi++)
            #pragma unroll
            for (int ni = 0; ni < 2; ni++)
                #pragma unroll
                for (int j = 0; j < 4; j++) {
                    int px = px0 + mi * 16 + (lane >> 2) + ((j >> 1) << 3);
                    int c  = n0 + ni * 8 + 2 * (lane & 3) + (j & 1);
                    s.u.sD[px * SDS + c] = d[mi][ni][j] + s.sbias[c];
                }
        __syncthreads();

        // flush -> g_dw[(pix)*9 + p][c], coalesced
        #pragma unroll
        for (int it = 0; it < 4; it++) {
            int idx = tid + it * NTH;           // 2048 float4
            int px = idx >> 4, c4 = idx & 15;
            float4 v = *(const float4*)&s.u.sD[px * SDS + c4 * 4];
            *((float4*)(g_dw + ((pix0 + px) * 9 + p) * 64) + c4) = v;
        }
    }
    __syncthreads();                            // g_dw of this block fully written

    // ===================== tail: gather + double softmax -> xc ====================
    {
        const int c   = tid & 63;
        const int pxg = tid >> 6;               // 0..7
        const float sg = __ldg(sigmar + c);
        #pragma unroll 1
        for (int it = 0; it < 16; it++) {
            const int px  = pxg * 16 + it;
            const int pix = pix0 + px;
            const int iy = s.iy[px], ix = s.ix[px];

            float dwv[9], h[9];
            #pragma unroll
            for (int t = 0; t < 9; t++)
                dwv[t] = __ldg(g_dw + (pix * 9 + t) * 64 + c);
            #pragma unroll
            for (int t = 0; t < 9; t++) {
                int yy = iy + t / 3 - 1;
                int xx = ix + t % 3 - 1;
                bool ok = ((unsigned)yy < HI) && ((unsigned)xx < WI);
                h[t] = ok ? __ldg(&g_xt[(yy * WI + xx) * 64 + c]) : 0.f;
            }

            float m = dwv[0];
            #pragma unroll
            for (int t = 1; t < 9; t++) m = fmaxf(m, dwv[t]);
            float es = 0.f, hm = 0.f;
            #pragma unroll
            for (int t = 0; t < 9; t++) {
                float e = __expf(dwv[t] - m);
                es += e;
                hm  = fmaf(h[t], e, hm);
            }
            float mean = hm / es;

            float bw[9], m2 = -3.4e38f;
            #pragma unroll
            for (int t = 0; t < 9; t++) {
                float dd = h[t] - mean;
                bw[t] = fmaf(sg * dd, dd, dwv[t]);
                m2 = fmaxf(m2, bw[t]);
            }
            float s2 = 0.f, xcv = 0.f;
            #pragma unroll
            for (int t = 0; t < 9; t++) {
                float ee = __expf(bw[t] - m2);
                s2  += ee;
                xcv  = fmaf(h[t], ee, xcv);
            }
            s.xc[px * XCS + c] = xcv / s2;
        }
    }
    __syncthreads();

    // ===================== PW branch (pfr holds pw2h och0) =====================
    layers12(s, pw_w1, pw_b1, g_pw2h, pw_b2, tid, pfr, g_pw3h, 3 * 256);

    // layer 3: 3 phases; contract with xc in-block, write out directly
    for (int p = 0; p < 3; p++) {
        for (int kc = 0; kc < 2; kc++) {
            __syncthreads();
            sts3(s.wt, tid, pfr);
            if (kc == 0)    pf3(g_pw3h + p * 256 + 128, 3 * 256, tid, pfr);
            else if (p < 2) pf3(g_pw3h + (p + 1) * 256, 3 * 256, tid, pfr);
            if (kc == 0 && tid < 64) s.sbias[tid] = __ldg(pw_b3 + tid * 3 + p);
            __syncthreads();

            if (kc == 0) {
                #pragma unroll
                for (int mi = 0; mi < 2; mi++)
                    #pragma unroll
                    for (int ni = 0; ni < 2; ni++)
                        #pragma unroll
                        for (int j = 0; j < 4; j++) d[mi][ni][j] = 0.f;
            }
            warp_gemm_h<H2SH, 8>(s.h2, s.wt, d, px0, n0, lane, kc * 128);
        }

        // stage D (+bias)
        #pragma unroll
        for (int mi = 0; mi < 2; mi++)
            #pragma unroll
            for (int ni = 0; ni < 2; ni++)
                #pragma unroll
                for (int j = 0; j < 4; j++) {
                    int px = px0 + mi * 16 + (lane >> 2) + ((j >> 1) << 3);
                    int c  = n0 + ni * 8 + 2 * (lane & 3) + (j & 1);
                    s.u.sD[px * SDS + c] = d[mi][ni][j] + s.sbias[c];
                }
        __syncthreads();

        // contract: out[p][pix0+px] = sum_c xc[px][c] * sD[px][c]
        {
            const int px2 = tid >> 2;            // 0..127
            const int q   = tid & 3;
            const float* row = &s.u.sD[px2 * SDS + q * 16];
            const float* xr  = &s.xc[px2 * XCS + q * 16];
            float acc = 0.f;
            #pragma unroll
            for (int cc = 0; cc < 16; cc++)
                acc = fmaf(row[cc], xr[cc], acc);
            acc += __shfl_xor_sync(0xffffffffu, acc, 1);
            acc += __shfl_xor_sync(0xffffffffu, acc, 2);
            if (q == 0)
                out[p * NPIX + pix0 + px2] = acc;
        }
    }
}

extern "C" void kernel_launch(void* const* d_in, const int* in_sizes, int n_in,
                              void* d_out, int out_size) {
    (void)in_sizes; (void)n_in; (void)out_size;
    const float* x      = (const float*)d_in[0];
    const float* pose   = (const float*)d_in[1];
    const int*   imY    = (const int*)  d_in[2];
    const int*   imX    = (const int*)  d_in[3];
    const float* sigmar = (const float*)d_in[4];
    const float* dw_w1  = (const float*)d_in[5];
    const float* dw_b1  = (const float*)d_in[6];
    const float* dw_w2  = (const float*)d_in[7];
    const float* dw_b2  = (const float*)d_in[8];
    const float* dw_w3  = (const float*)d_in[9];
    const float* dw_b3  = (const float*)d_in[10];
    const float* pw_w1  = (const float*)d_in[11];
    const float* pw_b1  = (const float*)d_in[12];
    const float* pw_w2  = (const float*)d_in[13];
    const float* pw_b2  = (const float*)d_in[14];
    const float* pw_w3  = (const float*)d_in[15];
    const float* pw_b3  = (const float*)d_in[16];
    float* out = (float*)d_out;

    const int tsmem = 64 * 257 * 4;
    cudaFuncSetAttribute(transpose_x_kernel,
                         cudaFuncAttributeMaxDynamicSharedMemorySize, tsmem);
    transpose_x_kernel<<<256, 256, tsmem>>>(x);

    conv_weights_kernel<<<256, 256>>>(dw_w2, dw_w3, pw_w2, pw_w3);

    const int asmem = (int)sizeof(SmemA);
    cudaFuncSetAttribute(biup_fused,
                         cudaFuncAttributeMaxDynamicSharedMemorySize, asmem);
    biup_fused<<<NPIX / PPB, NTH, asmem>>>(
        pose, imY, imX, sigmar,
        dw_w1, dw_b1, dw_b2, dw_b3,
        pw_w1, pw_b1, pw_b2, pw_b3,
        out);
}

// round 13
// speedup vs baseline: 2.0072x; 1.1410x over previous
#include <cuda_runtime.h>
#include <cuda_fp16.h>
#include <math.h>

#define HI    256
#define WI    256
#define NPIX  262144
#define PPB   128
#define NTH   512

#define H2SH  264     // h2 fp16 stride (528B): word-stride%32=4 -> conflict-free frags
#define H1SH  72      // h1 fp16 stride (144B): %32=4
#define WTSH  136     // weight tile fp16 stride (272B): %32=4
#define WTBUF (64 * WTSH)
#define SDS   68      // sD f32 staging stride
#define XCS   65      // xc f32 stride

typedef unsigned int u32;

__device__ float  g_xt[HI * WI * 64];     // x transposed [y][x][c]
__device__ __half g_dwh[NPIX * 9 * 64];   // dw scratch fp16 [pix][t][c]
__device__ __half g_dw2h[256 * 64];
__device__ __half g_dw3h[576 * 256];
__device__ __half g_pw2h[256 * 64];
__device__ __half g_pw3h[192 * 256];

struct __align__(16) SmemA {
    __half h2[PPB * H2SH];                     // 67584 B
    __half wt[2 * WTBUF];                      // 34816 B (double-buffered)
    union { __half h1[PPB * H1SH]; float sD[PPB * SDS]; } u;  // 34816 B
    float xc[PPB * XCS];                       // 33280 B
    float pose[3][PPB];                        //  1536 B
    int   iy[PPB];                             //   512 B
    int   ix[PPB];                             //   512 B
    float sbias[64];
    float sbias2[64];
};                                             // 173568 B

static __device__ __forceinline__ u32 ph2(float a, float b) {
    __half2 h = __floats2half2_rn(a, b);
    return *reinterpret_cast<u32*>(&h);
}

static __device__ __forceinline__ void mma_f16(float d[4], const u32 a[4], const u32 b[2]) {
    asm volatile(
        "mma.sync.aligned.m16n8k16.row.col.f32.f16.f16.f32 "
        "{%0,%1,%2,%3}, {%4,%5,%6,%7}, {%8,%9}, {%0,%1,%2,%3};"
        : "+f"(d[0]), "+f"(d[1]), "+f"(d[2]), "+f"(d[3])
        : "r"(a[0]), "r"(a[1]), "r"(a[2]), "r"(a[3]), "r"(b[0]), "r"(b[1]));
}

// ======== prep: transpose x AND convert weights (single launch) ========
__global__ void __launch_bounds__(256)
prep_kernel(const float* __restrict__ x,
            const float* __restrict__ dw2, const float* __restrict__ dw3,
            const float* __restrict__ pw2, const float* __restrict__ pw3) {
    extern __shared__ float tile[];   // [64][257]
    const int y   = blockIdx.x;
    const int tid = threadIdx.x;
    for (int i = tid; i < 64 * 256; i += 256) {
        int c = i >> 8, xx = i & 255;
        tile[c * 257 + xx] = __ldg(x + c * 65536 + y * 256 + xx);
    }
    __syncthreads();
    for (int i = tid; i < 64 * 256; i += 256) {
        int xx = i >> 6, c = i & 63;
        g_xt[(y * 256 + xx) * 64 + c] = tile[c * 257 + xx];
    }
    // weight conversion, grid-strided
    int i0 = blockIdx.x * 256 + tid;
    int n  = gridDim.x * 256;
    for (int k = i0; k < 256 * 64; k += n) g_dw2h[k] = __float2half_rn(__ldg(dw2 + k));
    for (int k = i0; k < 576 * 256; k += n) g_dw3h[k] = __float2half_rn(__ldg(dw3 + k));
    for (int k = i0; k < 256 * 64; k += n) g_pw2h[k] = __float2half_rn(__ldg(pw2 + k));
    for (int k = i0; k < 192 * 256; k += n) g_pw3h[k] = __float2half_rn(__ldg(pw3 + k));
}

// ======== weight prefetch/commit ========
static __device__ __forceinline__ void pf2(const __half* __restrict__ base,
                                           int tid, uint4 r[2]) {
    r[0] = __ldg((const uint4*)(base + (tid >> 3) * 64) + (tid & 7));
}
static __device__ __forceinline__ void sts2(__half* __restrict__ wt, int tid,
                                            const uint4 r[2]) {
    *(uint4*)&wt[(tid >> 3) * WTSH + (tid & 7) * 8] = r[0];
}
static __device__ __forceinline__ void pf3(const __half* __restrict__ base, int rs,
                                           int tid, uint4 r[2]) {
    #pragma unroll
    for (int it = 0; it < 2; it++) {
        int idx = tid + it * NTH;
        r[it] = __ldg((const uint4*)(base + (idx >> 4) * rs) + (idx & 15));
    }
}
static __device__ __forceinline__ void sts3(__half* __restrict__ wt, int tid,
                                            const uint4 r[2]) {
    #pragma unroll
    for (int it = 0; it < 2; it++) {
        int idx = tid + it * NTH;
        *(uint4*)&wt[(idx >> 4) * WTSH + (idx & 15) * 8] = r[it];
    }
}

// ======== warp GEMM: 32px x 16n, fp16 m16n8k16 ========
template<int ASH, int NKS>
static __device__ __forceinline__ void warp_gemm_h(const __half* __restrict__ A,
                                                   const __half* __restrict__ W,
                                                   float d[2][2][4],
                                                   int px0, int n0, int lane, int acol0)
{
    const __half* a0p = A + (px0 + (lane >> 2)) * ASH + acol0 + (lane & 3) * 2;
    const __half* b0p = W + (n0 + (lane >> 2)) * WTSH + (lane & 3) * 2;
    #pragma unroll
    for (int ks = 0; ks < NKS; ks++) {
        u32 a[2][4], b[2][2];
        #pragma unroll
        for (int mi = 0; mi < 2; mi++) {
            const __half* ap = a0p + mi * 16 * ASH + ks * 16;
            a[mi][0] = *(const u32*)(ap);
            a[mi][1] = *(const u32*)(ap + 8 * ASH);
            a[mi][2] = *(const u32*)(ap + 8);
            a[mi][3] = *(const u32*)(ap + 8 * ASH + 8);
        }
        #pragma unroll
        for (int ni = 0; ni < 2; ni++) {
            const __half* bp = b0p + ni * 8 * WTSH + ks * 16;
            b[ni][0] = *(const u32*)(bp);
            b[ni][1] = *(const u32*)(bp + 8);
        }
        #pragma unroll
        for (int mi = 0; mi < 2; mi++)
            #pragma unroll
            for (int ni = 0; ni < 2; ni++)
                mma_f16(d[mi][ni], a[mi], b[ni]);
    }
}

// ======== layers 1+2; pfr holds w2h och0 on entry, nextw chunk0 on exit ========
static __device__ void layers12(SmemA& s,
                                const float* __restrict__ w1, const float* __restrict__ b1,
                                const __half* __restrict__ w2h, const float* __restrict__ b2,
                                int tid, uint4 pfr[2], int& bi,
                                const __half* __restrict__ nextw, int nextrs)
{
    const int warp = tid >> 5, lane = tid & 31;
    const int px0 = (warp & 3) * 32;
    const int n0  = (warp >> 2) * 16;

    // layer 1 (scalar) -> h1 fp16
    {
        int o = tid & 63, pb = tid >> 6;
        float wa = __ldg(w1 + o * 3 + 0);
        float wb = __ldg(w1 + o * 3 + 1);
        float wc = __ldg(w1 + o * 3 + 2);
        float bb = __ldg(b1 + o);
        #pragma unroll 4
        for (int p = pb * 16; p < pb * 16 + 16; p++) {
            float v = fmaf(wa, s.pose[0][p],
                      fmaf(wb, s.pose[1][p],
                      fmaf(wc, s.pose[2][p], bb)));
            s.u.h1[p * H1SH + o] = __float2half_rn(fmaxf(v, 0.f));
        }
    }

    // layer 2: 4 o-chunks of 64, K=64 — one sync per stage (double-buffered wt)
    for (int och = 0; och < 4; och++) {
        __half* w = s.wt + bi * WTBUF;
        sts2(w, tid, pfr);
        bi ^= 1;
        if (och < 3) pf2(w2h + (och + 1) * 4096, tid, pfr);
        else         pf3(nextw, nextrs, tid, pfr);
        if (tid < 64) s.sbias2[tid] = __ldg(b2 + och * 64 + tid);
        __syncthreads();

        float d[2][2][4];
        #pragma unroll
        for (int mi = 0; mi < 2; mi++)
            #pragma unroll
            for (int ni = 0; ni < 2; ni++)
                #pragma unroll
                for (int j = 0; j < 4; j++) d[mi][ni][j] = 0.f;

        warp_gemm_h<H1SH, 4>(s.u.h1, w, d, px0, n0, lane, 0);

        #pragma unroll
        for (int mi = 0; mi < 2; mi++)
            #pragma unroll
            for (int ni = 0; ni < 2; ni++) {
                int px  = px0 + mi * 16 + (lane >> 2);
                int olb = n0 + ni * 8 + 2 * (lane & 3);
                float b0v = s.sbias2[olb], b1v = s.sbias2[olb + 1];
                u32 v01 = ph2(fmaxf(d[mi][ni][0] + b0v, 0.f),
                              fmaxf(d[mi][ni][1] + b1v, 0.f));
                *(u32*)&s.h2[px * H2SH + och * 64 + olb] = v01;
                u32 v23 = ph2(fmaxf(d[mi][ni][2] + b0v, 0.f),
                              fmaxf(d[mi][ni][3] + b1v, 0.f));
                *(u32*)&s.h2[(px + 8) * H2SH + och * 64 + olb] = v23;
            }
    }
}

// ======== per-channel double-softmax tail (scalar helper) ========
static __device__ __forceinline__ float tail1(const float* dwv, const float* h, float sg) {
    float m = dwv[0];
    #pragma unroll
    for (int t = 1; t < 9; t++) m = fmaxf(m, dwv[t]);
    float es = 0.f, hm = 0.f;
    #pragma unroll
    for (int t = 0; t < 9; t++) {
        float e = __expf(dwv[t] - m);
        es += e;
        hm  = fmaf(h[t], e, hm);
    }
    float mean = hm / es;
    float bw[9], m2 = -3.4e38f;
    #pragma unroll
    for (int t = 0; t < 9; t++) {
        float dd = h[t] - mean;
        bw[t] = fmaf(sg * dd, dd, dwv[t]);
        m2 = fmaxf(m2, bw[t]);
    }
    float s2 = 0.f, xcv = 0.f;
    #pragma unroll
    for (int t = 0; t < 9; t++) {
        float ee = __expf(bw[t] - m2);
        s2  += ee;
        xcv  = fmaf(h[t], ee, xcv);
    }
    return xcv / s2;
}

__global__ void __launch_bounds__(NTH, 1)
biup_fused(const float* __restrict__ poseMap,
           const int*   __restrict__ imY, const int* __restrict__ imX,
           const float* __restrict__ sigmar,
           const float* __restrict__ dw_w1, const float* __restrict__ dw_b1,
           const float* __restrict__ dw_b2, const float* __restrict__ dw_b3,
           const float* __restrict__ pw_w1, const float* __restrict__ pw_b1,
           const float* __restrict__ pw_b2, const float* __restrict__ pw_b3,
           float* __restrict__ out)
{
    extern __shared__ __align__(16) unsigned char smem_raw[];
    SmemA& s = *reinterpret_cast<SmemA*>(smem_raw);
    const int tid  = threadIdx.x;
    const int warp = tid >> 5, lane = tid & 31;
    const int px0 = (warp & 3) * 32;
    const int n0  = (warp >> 2) * 16;
    const int pix0 = blockIdx.x * PPB;

    uint4 pfr[2];
    pf2(g_dw2h, tid, pfr);                      // chain head
    int bi = 0;

    if (tid < 3 * PPB) {
        int j = tid >> 7, pp = tid & 127;
        s.pose[j][pp] = __ldg(poseMap + j * NPIX + pix0 + pp);
    }
    if (tid < PPB)           s.iy[tid]       = __ldg(imY + pix0 + tid);
    else if (tid < 2 * PPB)  s.ix[tid - PPB] = __ldg(imX + pix0 + tid - PPB);
    __syncthreads();

    // ===================== DW branch =====================
    layers12(s, dw_w1, dw_b1, g_dw2h, dw_b2, tid, pfr, bi, g_dw3h, 9 * 256);

    // layer 3: 9 tap phases, K=256 in 2 chunks of 128 -> g_dwh (fp16, with bias)
    float d[2][2][4];
    for (int p = 0; p < 9; p++) {
        for (int kc = 0; kc < 2; kc++) {
            __half* w = s.wt + bi * WTBUF;
            sts3(w, tid, pfr);
            bi ^= 1;
            if (kc == 0)    pf3(g_dw3h + p * 256 + 128, 9 * 256, tid, pfr);
            else if (p < 8) pf3(g_dw3h + (p + 1) * 256, 9 * 256, tid, pfr);
            else            pf2(g_pw2h, tid, pfr);          // chain into PW branch
            if (kc == 0 && tid < 64) s.sbias[tid] = __ldg(dw_b3 + tid * 9 + p);
            __syncthreads();

            if (kc == 0) {
                #pragma unroll
                for (int mi = 0; mi < 2; mi++)
                    #pragma unroll
                    for (int ni = 0; ni < 2; ni++)
                        #pragma unroll
                        for (int j = 0; j < 4; j++) d[mi][ni][j] = 0.f;
            }
            warp_gemm_h<H2SH, 8>(s.h2, w, d, px0, n0, lane, kc * 128);
        }

        // stage D (+bias) -> sD[px][c]
        #pragma unroll
        for (int mi = 0; mi < 2; mi++)
            #pragma unroll
            for (int ni = 0; ni < 2; ni++)
                #pragma unroll
                for (int j = 0; j < 4; j++) {
                    int px = px0 + mi * 16 + (lane >> 2) + ((j >> 1) << 3);
                    int c  = n0 + ni * 8 + 2 * (lane & 3) + (j & 1);
                    s.u.sD[px * SDS + c] = d[mi][ni][j] + s.sbias[c];
                }
        __syncthreads();

        // flush fp16 -> g_dwh[(pix)*9 + p][c], coalesced (1024 tasks of 8 halfs)
        #pragma unroll
        for (int it = 0; it < 2; it++) {
            int idx = tid + it * NTH;
            int px = idx >> 3, c8 = idx & 7;
            const float* sp = &s.u.sD[px * SDS + c8 * 8];
            float4 v0 = *(const float4*)sp;
            float4 v1 = *(const float4*)(sp + 4);
            uint4 st;
            st.x = ph2(v0.x, v0.y); st.y = ph2(v0.z, v0.w);
            st.z = ph2(v1.x, v1.y); st.w = ph2(v1.z, v1.w);
            *(uint4*)&g_dwh[((pix0 + px) * 9 + p) * 64 + c8 * 8] = st;
        }
        // next stage's sync orders flush vs sD reuse
    }
    __syncthreads();                            // g_dwh fully written (block-local)

    // ========== tail: c-pair threads; gather + double softmax -> xc ==========
    {
        const int cp  = tid & 31;               // channel pair
        const int c0  = 2 * cp;
        const int pxb = tid >> 5;               // 0..15
        const float sg0 = __ldg(sigmar + c0);
        const float sg1 = __ldg(sigmar + c0 + 1);
        #pragma unroll 1
        for (int it = 0; it < 8; it++) {
            const int px  = pxb + it * 16;
            const int pix = pix0 + px;
            const int iy = s.iy[px], ix = s.ix[px];

            float dv0[9], dv1[9], h0[9], h1v[9];
            #pragma unroll
            for (int t = 0; t < 9; t++) {
                __half2 hh = *(const __half2*)&g_dwh[(pix * 9 + t) * 64 + c0];
                float2 f = __half22float2(hh);
                dv0[t] = f.x; dv1[t] = f.y;
            }
            #pragma unroll
            for (int t = 0; t < 9; t++) {
                int yy = iy + t / 3 - 1;
                int xx = ix + t % 3 - 1;
                bool ok = ((unsigned)yy < HI) && ((unsigned)xx < WI);
                if (ok) {
                    float2 hv = *(const float2*)&g_xt[(yy * WI + xx) * 64 + c0];
                    h0[t] = hv.x; h1v[t] = hv.y;
                } else { h0[t] = 0.f; h1v[t] = 0.f; }
            }
            s.xc[px * XCS + c0]     = tail1(dv0, h0,  sg0);
            s.xc[px * XCS + c0 + 1] = tail1(dv1, h1v, sg1);
        }
    }
    __syncthreads();

    // ===================== PW branch (pfr holds pw2h och0) =====================
    layers12(s, pw_w1, pw_b1, g_pw2h, pw_b2, tid, pfr, bi, g_pw3h, 3 * 256);

    // layer 3: 3 phases; contract with xc in-block, write out directly
    for (int p = 0; p < 3; p++) {
        for (int kc = 0; kc < 2; kc++) {
            __half* w = s.wt + bi * WTBUF;
            sts3(w, tid, pfr);
            bi ^= 1;
            if (kc == 0)    pf3(g_pw3h + p * 256 + 128, 3 * 256, tid, pfr);
            else if (p < 2) pf3(g_pw3h + (p + 1) * 256, 3 * 256, tid, pfr);
            if (kc == 0 && tid < 64) s.sbias[tid] = __ldg(pw_b3 + tid * 3 + p);
            __syncthreads();

            if (kc == 0) {
                #pragma unroll
                for (int mi = 0; mi < 2; mi++)
                    #pragma unroll
                    for (int ni = 0; ni < 2; ni++)
                        #pragma unroll
                        for (int j = 0; j < 4; j++) d[mi][ni][j] = 0.f;
            }
            warp_gemm_h<H2SH, 8>(s.h2, w, d, px0, n0, lane, kc * 128);
        }

        // stage D (+bias)
        #pragma unroll
        for (int mi = 0; mi < 2; mi++)
            #pragma unroll
            for (int ni = 0; ni < 2; ni++)
                #pragma unroll
                for (int j = 0; j < 4; j++) {
                    int px = px0 + mi * 16 + (lane >> 2) + ((j >> 1) << 3);
                    int c  = n0 + ni * 8 + 2 * (lane & 3) + (j & 1);
                    s.u.sD[px * SDS + c] = d[mi][ni][j] + s.sbias[c];
                }
        __syncthreads();

        // contract: out[p][pix0+px] = sum_c xc[px][c] * sD[px][c]
        {
            const int px2 = tid >> 2;            // 0..127
            const int q   = tid & 3;
            const float* row = &s.u.sD[px2 * SDS + q * 16];
            const float* xr  = &s.xc[px2 * XCS + q * 16];
            float acc = 0.f;
            #pragma unroll
            for (int cc = 0; cc < 16; cc++)
                acc = fmaf(row[cc], xr[cc], acc);
            acc += __shfl_xor_sync(0xffffffffu, acc, 1);
            acc += __shfl_xor_sync(0xffffffffu, acc, 2);
            if (q == 0)
                out[p * NPIX + pix0 + px2] = acc;
        }
        // next stage's sync orders contraction vs sD reuse
    }
}

extern "C" void kernel_launch(void* const* d_in, const int* in_sizes, int n_in,
                              void* d_out, int out_size) {
    (void)in_sizes; (void)n_in; (void)out_size;
    const float* x      = (const float*)d_in[0];
    const float* pose   = (const float*)d_in[1];
    const int*   imY    = (const int*)  d_in[2];
    const int*   imX    = (const int*)  d_in[3];
    const float* sigmar = (const float*)d_in[4];
    const float* dw_w1  = (const float*)d_in[5];
    const float* dw_b1  = (const float*)d_in[6];
    const float* dw_w2  = (const float*)d_in[7];
    const float* dw_b2  = (const float*)d_in[8];
    const float* dw_w3  = (const float*)d_in[9];
    const float* dw_b3  = (const float*)d_in[10];
    const float* pw_w1  = (const float*)d_in[11];
    const float* pw_b1  = (const float*)d_in[12];
    const float* pw_w2  = (const float*)d_in[13];
    const float* pw_b2  = (const float*)d_in[14];
    const float* pw_w3  = (const float*)d_in[15];
    const float* pw_b3  = (const float*)d_in[16];
    float* out = (float*)d_out;

    const int tsmem = 64 * 257 * 4;
    cudaFuncSetAttribute(prep_kernel,
                         cudaFuncAttributeMaxDynamicSharedMemorySize, tsmem);
    prep_kernel<<<256, 256, tsmem>>>(x, dw_w2, dw_w3, pw_w2, pw_w3);

    const int asmem = (int)sizeof(SmemA);
    cudaFuncSetAttribute(biup_fused,
                         cudaFuncAttributeMaxDynamicSharedMemorySize, asmem);
    biup_fused<<<NPIX / PPB, NTH, asmem>>>(
        pose, imY, imX, sigmar,
        dw_w1, dw_b1, dw_b2, dw_b3,
        pw_w1, pw_b1, pw_b2, pw_b3,
        out);
}

// round 15
// speedup vs baseline: 2.1457x; 1.0690x over previous
#include <cuda_runtime.h>
#include <cuda_fp16.h>
#include <math.h>

#define HI    256
#define WI    256
#define NPIX  262144
#define PPB   64
#define NTH   256

#define H2SH  264     // h2 fp16 stride (528B): word-stride%32=4 -> conflict-free frags
#define H1SH  72      // h1 fp16 stride (144B): %32=4
#define WTSH  136     // weight tile fp16 stride (272B): %32=4
#define WTBUF (64 * WTSH)
#define SDS   68      // sD f32 staging stride
#define XCS   65      // xc f32 stride

typedef unsigned int u32;

__device__ float  g_xt[HI * WI * 64];     // x transposed [y][x][c]
__device__ __half g_dwh[NPIX * 9 * 64];   // dw scratch fp16 [pix][t][c]
__device__ __half g_dw2h[256 * 64];
__device__ __half g_dw3h[576 * 256];
__device__ __half g_pw2h[256 * 64];
__device__ __half g_pw3h[192 * 256];

struct __align__(16) SmemA {
    __half h2[PPB * H2SH];                     // 33792 B
    __half wt[2 * WTBUF];                      // 34816 B (double-buffered)
    union { __half h1[PPB * H1SH]; float sD[PPB * SDS]; } u;  // 17408 B
    float xc[PPB * XCS];                       // 16640 B
    float pose[3][PPB];                        //   768 B
    int   iy[PPB];                             //   256 B
    int   ix[PPB];                             //   256 B
    float sbias[64];
    float sbias2[64];
};                                             // ~104.5 KB -> 2 blocks/SM

static __device__ __forceinline__ u32 ph2(float a, float b) {
    __half2 h = __floats2half2_rn(a, b);
    return *reinterpret_cast<u32*>(&h);
}

static __device__ __forceinline__ void mma_f16(float d[4], const u32 a[4], const u32 b[2]) {
    asm volatile(
        "mma.sync.aligned.m16n8k16.row.col.f32.f16.f16.f32 "
        "{%0,%1,%2,%3}, {%4,%5,%6,%7}, {%8,%9}, {%0,%1,%2,%3};"
        : "+f"(d[0]), "+f"(d[1]), "+f"(d[2]), "+f"(d[3])
        : "r"(a[0]), "r"(a[1]), "r"(a[2]), "r"(a[3]), "r"(b[0]), "r"(b[1]));
}

// ======== prep: transpose x AND convert weights (single launch) ========
__global__ void __launch_bounds__(256)
prep_kernel(const float* __restrict__ x,
            const float* __restrict__ dw2, const float* __restrict__ dw3,
            const float* __restrict__ pw2, const float* __restrict__ pw3) {
    extern __shared__ float tile[];   // [64][257]
    const int y   = blockIdx.x;
    const int tid = threadIdx.x;
    for (int i = tid; i < 64 * 256; i += 256) {
        int c = i >> 8, xx = i & 255;
        tile[c * 257 + xx] = __ldg(x + c * 65536 + y * 256 + xx);
    }
    __syncthreads();
    for (int i = tid; i < 64 * 256; i += 256) {
        int xx = i >> 6, c = i & 63;
        g_xt[(y * 256 + xx) * 64 + c] = tile[c * 257 + xx];
    }
    int i0 = blockIdx.x * 256 + tid;
    int n  = gridDim.x * 256;
    for (int k = i0; k < 256 * 64; k += n) g_dw2h[k] = __float2half_rn(__ldg(dw2 + k));
    for (int k = i0; k < 576 * 256; k += n) g_dw3h[k] = __float2half_rn(__ldg(dw3 + k));
    for (int k = i0; k < 256 * 64; k += n) g_pw2h[k] = __float2half_rn(__ldg(pw2 + k));
    for (int k = i0; k < 192 * 256; k += n) g_pw3h[k] = __float2half_rn(__ldg(pw3 + k));
}

// ======== weight prefetch/commit (256 threads) ========
// pf2: 64n x 64k fp16 = 8KB = 512 uint4 -> 2/thread
static __device__ __forceinline__ void pf2(const __half* __restrict__ base,
                                           int tid, uint4 r[4]) {
    #pragma unroll
    for (int it = 0; it < 2; it++) {
        int idx = tid + it * NTH;
        r[it] = __ldg((const uint4*)(base + (idx >> 3) * 64) + (idx & 7));
    }
}
static __device__ __forceinline__ void sts2(__half* __restrict__ wt, int tid,
                                            const uint4 r[4]) {
    #pragma unroll
    for (int it = 0; it < 2; it++) {
        int idx = tid + it * NTH;
        *(uint4*)&wt[(idx >> 3) * WTSH + (idx & 7) * 8] = r[it];
    }
}
// pf3: 64n x 128k fp16 = 16KB = 1024 uint4 -> 4/thread
static __device__ __forceinline__ void pf3(const __half* __restrict__ base, int rs,
                                           int tid, uint4 r[4]) {
    #pragma unroll
    for (int it = 0; it < 4; it++) {
        int idx = tid + it * NTH;
        r[it] = __ldg((const uint4*)(base + (idx >> 4) * rs) + (idx & 15));
    }
}
static __device__ __forceinline__ void sts3(__half* __restrict__ wt, int tid,
                                            const uint4 r[4]) {
    #pragma unroll
    for (int it = 0; it < 4; it++) {
        int idx = tid + it * NTH;
        *(uint4*)&wt[(idx >> 4) * WTSH + (idx & 15) * 8] = r[it];
    }
}

// ======== warp GEMM: 32px x 16n, fp16 m16n8k16 ========
template<int ASH, int NKS>
static __device__ __forceinline__ void warp_gemm_h(const __half* __restrict__ A,
                                                   const __half* __restrict__ W,
                                                   float d[2][2][4],
                                                   int px0, int n0, int lane, int acol0)
{
    const __half* a0p = A + (px0 + (lane >> 2)) * ASH + acol0 + (lane & 3) * 2;
    const __half* b0p = W + (n0 + (lane >> 2)) * WTSH + (lane & 3) * 2;
    #pragma unroll
    for (int ks = 0; ks < NKS; ks++) {
        u32 a[2][4], b[2][2];
        #pragma unroll
        for (int mi = 0; mi < 2; mi++) {
            const __half* ap = a0p + mi * 16 * ASH + ks * 16;
            a[mi][0] = *(const u32*)(ap);
            a[mi][1] = *(const u32*)(ap + 8 * ASH);
            a[mi][2] = *(const u32*)(ap + 8);
            a[mi][3] = *(const u32*)(ap + 8 * ASH + 8);
        }
        #pragma unroll
        for (int ni = 0; ni < 2; ni++) {
            const __half* bp = b0p + ni * 8 * WTSH + ks * 16;
            b[ni][0] = *(const u32*)(bp);
            b[ni][1] = *(const u32*)(bp + 8);
        }
        #pragma unroll
        for (int mi = 0; mi < 2; mi++)
            #pragma unroll
            for (int ni = 0; ni < 2; ni++)
                mma_f16(d[mi][ni], a[mi], b[ni]);
    }
}

// ======== layers 1+2; pfr holds w2h och0 on entry, nextw chunk0 on exit ========
static __device__ void layers12(SmemA& s,
                                const float* __restrict__ w1, const float* __restrict__ b1,
                                const __half* __restrict__ w2h, const float* __restrict__ b2,
                                int tid, uint4 pfr[4], int& bi,
                                const __half* __restrict__ nextw, int nextrs)
{
    const int warp = tid >> 5, lane = tid & 31;
    const int px0 = (warp & 1) * 32;
    const int n0  = (warp >> 1) * 16;

    // layer 1 (scalar) -> h1 fp16
    {
        int o = tid & 63, pb = tid >> 6;       // 4 groups of 16 px
        float wa = __ldg(w1 + o * 3 + 0);
        float wb = __ldg(w1 + o * 3 + 1);
        float wc = __ldg(w1 + o * 3 + 2);
        float bb = __ldg(b1 + o);
        #pragma unroll 4
        for (int p = pb * 16; p < pb * 16 + 16; p++) {
            float v = fmaf(wa, s.pose[0][p],
                      fmaf(wb, s.pose[1][p],
                      fmaf(wc, s.pose[2][p], bb)));
            s.u.h1[p * H1SH + o] = __float2half_rn(fmaxf(v, 0.f));
        }
    }

    // layer 2: 4 o-chunks of 64, K=64 — one sync per stage (double-buffered wt)
    for (int och = 0; och < 4; och++) {
        __half* w = s.wt + bi * WTBUF;
        sts2(w, tid, pfr);
        bi ^= 1;
        if (och < 3) pf2(w2h + (och + 1) * 4096, tid, pfr);
        else         pf3(nextw, nextrs, tid, pfr);
        if (tid < 64) s.sbias2[tid] = __ldg(b2 + och * 64 + tid);
        __syncthreads();

        float d[2][2][4];
        #pragma unroll
        for (int mi = 0; mi < 2; mi++)
            #pragma unroll
            for (int ni = 0; ni < 2; ni++)
                #pragma unroll
                for (int j = 0; j < 4; j++) d[mi][ni][j] = 0.f;

        warp_gemm_h<H1SH, 4>(s.u.h1, w, d, px0, n0, lane, 0);

        #pragma unroll
        for (int mi = 0; mi < 2; mi++)
            #pragma unroll
            for (int ni = 0; ni < 2; ni++) {
                int px  = px0 + mi * 16 + (lane >> 2);
                int olb = n0 + ni * 8 + 2 * (lane & 3);
                float b0v = s.sbias2[olb], b1v = s.sbias2[olb + 1];
                u32 v01 = ph2(fmaxf(d[mi][ni][0] + b0v, 0.f),
                              fmaxf(d[mi][ni][1] + b1v, 0.f));
                *(u32*)&s.h2[px * H2SH + och * 64 + olb] = v01;
                u32 v23 = ph2(fmaxf(d[mi][ni][2] + b0v, 0.f),
                              fmaxf(d[mi][ni][3] + b1v, 0.f));
                *(u32*)&s.h2[(px + 8) * H2SH + och * 64 + olb] = v23;
            }
    }
}

// ======== per-channel double-softmax tail (scalar helper) ========
static __device__ __forceinline__ float tail1(const float* dwv, const float* h, float sg) {
    float m = dwv[0];
    #pragma unroll
    for (int t = 1; t < 9; t++) m = fmaxf(m, dwv[t]);
    float es = 0.f, hm = 0.f;
    #pragma unroll
    for (int t = 0; t < 9; t++) {
        float e = __expf(dwv[t] - m);
        es += e;
        hm  = fmaf(h[t], e, hm);
    }
    float mean = hm / es;
    float bw[9], m2 = -3.4e38f;
    #pragma unroll
    for (int t = 0; t < 9; t++) {
        float dd = h[t] - mean;
        bw[t] = fmaf(sg * dd, dd, dwv[t]);
        m2 = fmaxf(m2, bw[t]);
    }
    float s2 = 0.f, xcv = 0.f;
    #pragma unroll
    for (int t = 0; t < 9; t++) {
        float ee = __expf(bw[t] - m2);
        s2  += ee;
        xcv  = fmaf(h[t], ee, xcv);
    }
    return xcv / s2;
}

__global__ void __launch_bounds__(NTH, 2)
biup_fused(const float* __restrict__ poseMap,
           const int*   __restrict__ imY, const int* __restrict__ imX,
           const float* __restrict__ sigmar,
           const float* __restrict__ dw_w1, const float* __restrict__ dw_b1,
           const float* __restrict__ dw_b2, const float* __restrict__ dw_b3,
           const float* __restrict__ pw_w1, const float* __restrict__ pw_b1,
           const float* __restrict__ pw_b2, const float* __restrict__ pw_b3,
           float* __restrict__ out)
{
    extern __shared__ __align__(16) unsigned char smem_raw[];
    SmemA& s = *reinterpret_cast<SmemA*>(smem_raw);
    const int tid  = threadIdx.x;
    const int warp = tid >> 5, lane = tid & 31;
    const int px0 = (warp & 1) * 32;
    const int n0  = (warp >> 1) * 16;
    const int pix0 = blockIdx.x * PPB;

    uint4 pfr[4];
    pf2(g_dw2h, tid, pfr);                      // chain head
    int bi = 0;

    if (tid < 3 * PPB) {
        int j = tid >> 6, pp = tid & 63;
        s.pose[j][pp] = __ldg(poseMap + j * NPIX + pix0 + pp);
    }
    if (tid < PPB)           s.iy[tid]       = __ldg(imY + pix0 + tid);
    else if (tid < 2 * PPB)  s.ix[tid - PPB] = __ldg(imX + pix0 + tid - PPB);
    __syncthreads();

    // ===================== DW branch =====================
    layers12(s, dw_w1, dw_b1, g_dw2h, dw_b2, tid, pfr, bi, g_dw3h, 9 * 256);

    // layer 3: 9 tap phases, K=256 in 2 chunks of 128 -> g_dwh (fp16, with bias)
    float d[2][2][4];
    for (int p = 0; p < 9; p++) {
        for (int kc = 0; kc < 2; kc++) {
            __half* w = s.wt + bi * WTBUF;
            sts3(w, tid, pfr);
            bi ^= 1;
            if (kc == 0)    pf3(g_dw3h + p * 256 + 128, 9 * 256, tid, pfr);
            else if (p < 8) pf3(g_dw3h + (p + 1) * 256, 9 * 256, tid, pfr);
            else            pf2(g_pw2h, tid, pfr);          // chain into PW branch
            if (kc == 0 && tid < 64) s.sbias[tid] = __ldg(dw_b3 + tid * 9 + p);
            __syncthreads();

            if (kc == 0) {
                #pragma unroll
                for (int mi = 0; mi < 2; mi++)
                    #pragma unroll
                    for (int ni = 0; ni < 2; ni++)
                        #pragma unroll
                        for (int j = 0; j < 4; j++) d[mi][ni][j] = 0.f;
            }
            warp_gemm_h<H2SH, 8>(s.h2, w, d, px0, n0, lane, kc * 128);
        }

        // stage D (+bias) -> sD[px][c]
        #pragma unroll
        for (int mi = 0; mi < 2; mi++)
            #pragma unroll
            for (int ni = 0; ni < 2; ni++)
                #pragma unroll
                for (int j = 0; j < 4; j++) {
                    int px = px0 + mi * 16 + (lane >> 2) + ((j >> 1) << 3);
                    int c  = n0 + ni * 8 + 2 * (lane & 3) + (j & 1);
                    s.u.sD[px * SDS + c] = d[mi][ni][j] + s.sbias[c];
                }
        __syncthreads();

        // flush fp16 -> g_dwh[(pix)*9 + p][c]: 512 uint4, 2/thread
        #pragma unroll
        for (int it = 0; it < 2; it++) {
            int idx = tid + it * NTH;
            int px = idx >> 3, c8 = idx & 7;
            const float* sp = &s.u.sD[px * SDS + c8 * 8];
            float4 v0 = *(const float4*)sp;
            float4 v1 = *(const float4*)(sp + 4);
            uint4 st;
            st.x = ph2(v0.x, v0.y); st.y = ph2(v0.z, v0.w);
            st.z = ph2(v1.x, v1.y); st.w = ph2(v1.z, v1.w);
            *(uint4*)&g_dwh[((pix0 + px) * 9 + p) * 64 + c8 * 8] = st;
        }
        // next stage's sync orders flush vs sD reuse
    }
    __syncthreads();                            // g_dwh fully written (block-local)

    // ========== tail: c-pair threads; gather + double softmax -> xc ==========
    {
        const int cp  = tid & 31;               // channel pair
        const int c0  = 2 * cp;
        const int pxb = tid >> 5;               // 0..7
        const float sg0 = __ldg(sigmar + c0);
        const float sg1 = __ldg(sigmar + c0 + 1);
        #pragma unroll 1
        for (int it = 0; it < 8; it++) {
            const int px  = pxb + it * 8;
            const int pix = pix0 + px;
            const int iy = s.iy[px], ix = s.ix[px];

            float dv0[9], dv1[9], h0[9], h1v[9];
            #pragma unroll
            for (int t = 0; t < 9; t++) {
                __half2 hh = *(const __half2*)&g_dwh[(pix * 9 + t) * 64 + c0];
                float2 f = __half22float2(hh);
                dv0[t] = f.x; dv1[t] = f.y;
            }
            #pragma unroll
            for (int t = 0; t < 9; t++) {
                int yy = iy + t / 3 - 1;
                int xx = ix + t % 3 - 1;
                bool ok = ((unsigned)yy < HI) && ((unsigned)xx < WI);
                if (ok) {
                    float2 hv = *(const float2*)&g_xt[(yy * WI + xx) * 64 + c0];
                    h0[t] = hv.x; h1v[t] = hv.y;
                } else { h0[t] = 0.f; h1v[t] = 0.f; }
            }
            s.xc[px * XCS + c0]     = tail1(dv0, h0,  sg0);
            s.xc[px * XCS + c0 + 1] = tail1(dv1, h1v, sg1);
        }
    }
    __syncthreads();

    // ===================== PW branch (pfr holds pw2h och0) =====================
    layers12(s, pw_w1, pw_b1, g_pw2h, pw_b2, tid, pfr, bi, g_pw3h, 3 * 256);

    // layer 3: 3 phases; contract with xc in-block, write out directly
    for (int p = 0; p < 3; p++) {
        for (int kc = 0; kc < 2; kc++) {
            __half* w = s.wt + bi * WTBUF;
            sts3(w, tid, pfr);
            bi ^= 1;
            if (kc == 0)    pf3(g_pw3h + p * 256 + 128, 3 * 256, tid, pfr);
            else if (p < 2) pf3(g_pw3h + (p + 1) * 256, 3 * 256, tid, pfr);
            if (kc == 0 && tid < 64) s.sbias[tid] = __ldg(pw_b3 + tid * 3 + p);
            __syncthreads();

            if (kc == 0) {
                #pragma unroll
                for (int mi = 0; mi < 2; mi++)
                    #pragma unroll
                    for (int ni = 0; ni < 2; ni++)
                        #pragma unroll
                        for (int j = 0; j < 4; j++) d[mi][ni][j] = 0.f;
            }
            warp_gemm_h<H2SH, 8>(s.h2, w, d, px0, n0, lane, kc * 128);
        }

        // stage D (+bias)
        #pragma unroll
        for (int mi = 0; mi < 2; mi++)
            #pragma unroll
            for (int ni = 0; ni < 2; ni++)
                #pragma unroll
                for (int j = 0; j < 4; j++) {
                    int px = px0 + mi * 16 + (lane >> 2) + ((j >> 1) << 3);
                    int c  = n0 + ni * 8 + 2 * (lane & 3) + (j & 1);
                    s.u.sD[px * SDS + c] = d[mi][ni][j] + s.sbias[c];
                }
        __syncthreads();

        // contract: out[p][pix0+px] = sum_c xc[px][c] * sD[px][c]
        {
            const int px2 = tid >> 2;            // 0..63
            const int q   = tid & 3;
            const float* row = &s.u.sD[px2 * SDS + q * 16];
            const float* xr  = &s.xc[px2 * XCS + q * 16];
            float acc = 0.f;
            #pragma unroll
            for (int cc = 0; cc < 16; cc++)
                acc = fmaf(row[cc], xr[cc], acc);
            acc += __shfl_xor_sync(0xffffffffu, acc, 1);
            acc += __shfl_xor_sync(0xffffffffu, acc, 2);
            if (q == 0)
                out[p * NPIX + pix0 + px2] = acc;
        }
        // next stage's sync orders contraction vs sD reuse
    }
}

extern "C" void kernel_launch(void* const* d_in, const int* in_sizes, int n_in,
                              void* d_out, int out_size) {
    (void)in_sizes; (void)n_in; (void)out_size;
    const float* x      = (const float*)d_in[0];
    const float* pose   = (const float*)d_in[1];
    const int*   imY    = (const int*)  d_in[2];
    const int*   imX    = (const int*)  d_in[3];
    const float* sigmar = (const float*)d_in[4];
    const float* dw_w1  = (const float*)d_in[5];
    const float* dw_b1  = (const float*)d_in[6];
    const float* dw_w2  = (const float*)d_in[7];
    const float* dw_b2  = (const float*)d_in[8];
    const float* dw_w3  = (const float*)d_in[9];
    const float* dw_b3  = (const float*)d_in[10];
    const float* pw_w1  = (const float*)d_in[11];
    const float* pw_b1  = (const float*)d_in[12];
    const float* pw_w2  = (const float*)d_in[13];
    const float* pw_b2  = (const float*)d_in[14];
    const float* pw_w3  = (const float*)d_in[15];
    const float* pw_b3  = (const float*)d_in[16];
    float* out = (float*)d_out;

    const int tsmem = 64 * 257 * 4;
    cudaFuncSetAttribute(prep_kernel,
                         cudaFuncAttributeMaxDynamicSharedMemorySize, tsmem);
    prep_kernel<<<256, 256, tsmem>>>(x, dw_w2, dw_w3, pw_w2, pw_w3);

    const int asmem = (int)sizeof(SmemA);
    cudaFuncSetAttribute(biup_fused,
                         cudaFuncAttributeMaxDynamicSharedMemorySize, asmem);
    biup_fused<<<NPIX / PPB, NTH, asmem>>>(
        pose, imY, imX, sigmar,
        dw_w1, dw_b1, dw_b2, dw_b3,
        pw_w1, pw_b1, pw_b2, pw_b3,
        out);
}

// round 16
// speedup vs baseline: 2.3029x; 1.0733x over previous
#include <cuda_runtime.h>
#include <cuda_fp16.h>
#include <math.h>

#define HI    256
#define WI    256
#define NPIX  262144
#define PPB   64
#define NTH   256

#define H2SH  264     // h2 fp16 stride (528B): word stride %32 = 4 -> conflict-free
#define H1SH  72      // h1 fp16 stride
#define WT2S  72      // weight tile stride (64k + pad), words %32 = 4
#define WTPH  (64 * WT2S)     // one phase tile: 4608 halfs
#define WTBUF (2 * WTPH)      // one buffer (2 phases)
#define SDHS  72      // sDh fp16 stride
#define XCS   65      // xc f32 stride

typedef unsigned int u32;

__device__ float  g_xt[HI * WI * 64];     // x transposed [y][x][c]
__device__ __half g_dwh[NPIX * 9 * 64];   // dw scratch fp16 [pix][t][c]
__device__ __half g_dw2h[256 * 64];
__device__ __half g_dw3h[576 * 256];
__device__ __half g_pw2h[256 * 64];
__device__ __half g_pw3h[192 * 256];

struct __align__(16) SmemA {
    __half h2[PPB * H2SH];                     // 33792 B
    __half wt[2 * WTBUF];                      // 36864 B (2 buffers x 2 phases)
    union { __half h1[PPB * H1SH]; __half sDh[2][PPB * SDHS]; } u;  // 18432 B
    float xc[PPB * XCS];                       // 16640 B
    float pose[3][PPB];                        //   768 B
    int   iy[PPB];                             //   256 B
    int   ix[PPB];                             //   256 B
    float sbias[2][2][64];                     //  1024 B  (double-buffered, 2 phases)
};                                             // ~105.5 KB -> 2 blocks/SM

static __device__ __forceinline__ u32 ph2(float a, float b) {
    __half2 h = __floats2half2_rn(a, b);
    return *reinterpret_cast<u32*>(&h);
}

static __device__ __forceinline__ void mma_f16(float d[4], const u32 a[4], const u32 b[2]) {
    asm volatile(
        "mma.sync.aligned.m16n8k16.row.col.f32.f16.f16.f32 "
        "{%0,%1,%2,%3}, {%4,%5,%6,%7}, {%8,%9}, {%0,%1,%2,%3};"
        : "+f"(d[0]), "+f"(d[1]), "+f"(d[2]), "+f"(d[3])
        : "r"(a[0]), "r"(a[1]), "r"(a[2]), "r"(a[3]), "r"(b[0]), "r"(b[1]));
}

// ======== prep: transpose x AND convert weights (single launch) ========
__global__ void __launch_bounds__(256)
prep_kernel(const float* __restrict__ x,
            const float* __restrict__ dw2, const float* __restrict__ dw3,
            const float* __restrict__ pw2, const float* __restrict__ pw3) {
    extern __shared__ float tile[];   // [64][257]
    const int y   = blockIdx.x;
    const int tid = threadIdx.x;
    for (int i = tid; i < 64 * 256; i += 256) {
        int c = i >> 8, xx = i & 255;
        tile[c * 257 + xx] = __ldg(x + c * 65536 + y * 256 + xx);
    }
    __syncthreads();
    for (int i = tid; i < 64 * 256; i += 256) {
        int xx = i >> 6, c = i & 63;
        g_xt[(y * 256 + xx) * 64 + c] = tile[c * 257 + xx];
    }
    int i0 = blockIdx.x * 256 + tid;
    int n  = gridDim.x * 256;
    for (int k = i0; k < 256 * 64; k += n) g_dw2h[k] = __float2half_rn(__ldg(dw2 + k));
    for (int k = i0; k < 576 * 256; k += n) g_dw3h[k] = __float2half_rn(__ldg(dw3 + k));
    for (int k = i0; k < 256 * 64; k += n) g_pw2h[k] = __float2half_rn(__ldg(pw2 + k));
    for (int k = i0; k < 192 * 256; k += n) g_pw3h[k] = __float2half_rn(__ldg(pw3 + k));
}

// ======== paired weight prefetch/commit: two 64n x 64k chunks (8KB each) ========
static __device__ __forceinline__ void pf_pair(const __half* __restrict__ b0,
                                               const __half* __restrict__ b1,
                                               int rs, int tid, uint4 r[4]) {
    #pragma unroll
    for (int it = 0; it < 2; it++) {
        int idx = tid + it * NTH;
        int row = idx >> 3, k8 = idx & 7;
        r[it]     = __ldg((const uint4*)(b0 + row * rs) + k8);
        r[2 + it] = __ldg((const uint4*)(b1 + row * rs) + k8);
    }
}
static __device__ __forceinline__ void sts_pair(__half* __restrict__ wt, int tid,
                                                const uint4 r[4]) {
    #pragma unroll
    for (int it = 0; it < 2; it++) {
        int idx = tid + it * NTH;
        int row = idx >> 3, k8 = idx & 7;
        *(uint4*)&wt[row * WT2S + k8 * 8]        = r[it];
        *(uint4*)&wt[WTPH + row * WT2S + k8 * 8] = r[2 + it];
    }
}

// ======== warp GEMM: 32px x 32n, K=64 (4 x m16n8k16) ========
template<int ASH>
static __device__ __forceinline__ void warp_gemm32(const __half* __restrict__ A,
                                                   const __half* __restrict__ W,
                                                   float d[2][4][4],
                                                   int px0, int n0, int lane, int acol0)
{
    const __half* a0p = A + (px0 + (lane >> 2)) * ASH + acol0 + (lane & 3) * 2;
    const __half* b0p = W + (n0 + (lane >> 2)) * WT2S + (lane & 3) * 2;
    #pragma unroll
    for (int ks = 0; ks < 4; ks++) {
        u32 a[2][4], b[4][2];
        #pragma unroll
        for (int mi = 0; mi < 2; mi++) {
            const __half* ap = a0p + mi * 16 * ASH + ks * 16;
            a[mi][0] = *(const u32*)(ap);
            a[mi][1] = *(const u32*)(ap + 8 * ASH);
            a[mi][2] = *(const u32*)(ap + 8);
            a[mi][3] = *(const u32*)(ap + 8 * ASH + 8);
        }
        #pragma unroll
        for (int ni = 0; ni < 4; ni++) {
            const __half* bp = b0p + ni * 8 * WT2S + ks * 16;
            b[ni][0] = *(const u32*)(bp);
            b[ni][1] = *(const u32*)(bp + 8);
        }
        #pragma unroll
        for (int mi = 0; mi < 2; mi++)
            #pragma unroll
            for (int ni = 0; ni < 4; ni++)
                mma_f16(d[mi][ni], a[mi], b[ni]);
    }
}

static __device__ __forceinline__ void zero_d(float d[2][4][4]) {
    #pragma unroll
    for (int mi = 0; mi < 2; mi++)
        #pragma unroll
        for (int ni = 0; ni < 4; ni++)
            #pragma unroll
            for (int j = 0; j < 4; j++) d[mi][ni][j] = 0.f;
}

// ======== layers 1+2; pfr holds w2h (och0,och1) on entry, (nb0,nb1) on exit ====
static __device__ void layers12(SmemA& s,
                                const float* __restrict__ w1, const float* __restrict__ b1,
                                const __half* __restrict__ w2h, const float* __restrict__ b2,
                                int tid, uint4 pfr[4], int& bi,
                                const __half* __restrict__ nb0,
                                const __half* __restrict__ nb1, int nrs)
{
    const int warp = tid >> 5, lane = tid & 31;
    const int ph  = warp & 1;
    const int px0 = ((warp >> 1) & 1) * 32;
    const int n0  = (warp >> 2) * 32;

    // layer 1 (scalar) -> h1 fp16
    {
        int o = tid & 63, pb = tid >> 6;       // 4 groups of 16 px
        float wa = __ldg(w1 + o * 3 + 0);
        float wb = __ldg(w1 + o * 3 + 1);
        float wc = __ldg(w1 + o * 3 + 2);
        float bb = __ldg(b1 + o);
        #pragma unroll 4
        for (int p = pb * 16; p < pb * 16 + 16; p++) {
            float v = fmaf(wa, s.pose[0][p],
                      fmaf(wb, s.pose[1][p],
                      fmaf(wc, s.pose[2][p], bb)));
            s.u.h1[p * H1SH + o] = __float2half_rn(fmaxf(v, 0.f));
        }
    }

    // layer 2: 2 och-pair stages, K=64 each (phase ph handles och = op*2+ph)
    for (int op = 0; op < 2; op++) {
        __half* w = s.wt + bi * WTBUF;
        const int sb = bi;
        sts_pair(w, tid, pfr);
        bi ^= 1;
        if (op == 0) pf_pair(w2h + 2 * 4096, w2h + 3 * 4096, 64, tid, pfr);
        else         pf_pair(nb0, nb1, nrs, tid, pfr);
        if (tid < 128)
            s.sbias[sb][tid >> 6][tid & 63] =
                __ldg(b2 + (op * 2 + (tid >> 6)) * 64 + (tid & 63));
        __syncthreads();

        float d[2][4][4];
        zero_d(d);
        warp_gemm32<H1SH>(s.u.h1, w + ph * WTPH, d, px0, n0, lane, 0);

        const int och = op * 2 + ph;
        #pragma unroll
        for (int mi = 0; mi < 2; mi++)
            #pragma unroll
            for (int ni = 0; ni < 4; ni++) {
                int px  = px0 + mi * 16 + (lane >> 2);
                int olb = n0 + ni * 8 + 2 * (lane & 3);
                float b0v = s.sbias[sb][ph][olb], b1v = s.sbias[sb][ph][olb + 1];
                u32 v01 = ph2(fmaxf(d[mi][ni][0] + b0v, 0.f),
                              fmaxf(d[mi][ni][1] + b1v, 0.f));
                *(u32*)&s.h2[px * H2SH + och * 64 + olb] = v01;
                u32 v23 = ph2(fmaxf(d[mi][ni][2] + b0v, 0.f),
                              fmaxf(d[mi][ni][3] + b1v, 0.f));
                *(u32*)&s.h2[(px + 8) * H2SH + och * 64 + olb] = v23;
            }
    }
}

// ======== per-channel double-softmax tail ========
static __device__ __forceinline__ float tail1(const float* dwv, const float* h, float sg) {
    float m = dwv[0];
    #pragma unroll
    for (int t = 1; t < 9; t++) m = fmaxf(m, dwv[t]);
    float es = 0.f, hm = 0.f;
    #pragma unroll
    for (int t = 0; t < 9; t++) {
        float e = __expf(dwv[t] - m);
        es += e;
        hm  = fmaf(h[t], e, hm);
    }
    float mean = hm / es;
    float bw[9], m2 = -3.4e38f;
    #pragma unroll
    for (int t = 0; t < 9; t++) {
        float dd = h[t] - mean;
        bw[t] = fmaf(sg * dd, dd, dwv[t]);
        m2 = fmaxf(m2, bw[t]);
    }
    float s2 = 0.f, xcv = 0.f;
    #pragma unroll
    for (int t = 0; t < 9; t++) {
        float ee = __expf(bw[t] - m2);
        s2  += ee;
        xcv  = fmaf(h[t], ee, xcv);
    }
    return xcv / s2;
}

__global__ void __launch_bounds__(NTH, 2)
biup_fused(const float* __restrict__ poseMap,
           const int*   __restrict__ imY, const int* __restrict__ imX,
           const float* __restrict__ sigmar,
           const float* __restrict__ dw_w1, const float* __restrict__ dw_b1,
           const float* __restrict__ dw_b2, const float* __restrict__ dw_b3,
           const float* __restrict__ pw_w1, const float* __restrict__ pw_b1,
           const float* __restrict__ pw_b2, const float* __restrict__ pw_b3,
           float* __restrict__ out)
{
    extern __shared__ __align__(16) unsigned char smem_raw[];
    SmemA& s = *reinterpret_cast<SmemA*>(smem_raw);
    const int tid  = threadIdx.x;
    const int warp = tid >> 5, lane = tid & 31;
    const int ph  = warp & 1;
    const int px0 = ((warp >> 1) & 1) * 32;
    const int n0  = (warp >> 2) * 32;
    const int pix0 = blockIdx.x * PPB;

    uint4 pfr[4];
    pf_pair(g_dw2h, g_dw2h + 4096, 64, tid, pfr);   // chain head: dw2 och {0,1}
    int bi = 0;

    if (tid < 3 * PPB) {
        int j = tid >> 6, pp = tid & 63;
        s.pose[j][pp] = __ldg(poseMap + j * NPIX + pix0 + pp);
    }
    if (tid < PPB)           s.iy[tid]       = __ldg(imY + pix0 + tid);
    else if (tid < 2 * PPB)  s.ix[tid - PPB] = __ldg(imX + pix0 + tid - PPB);
    __syncthreads();

    // ===================== DW branch =====================
    layers12(s, dw_w1, dw_b1, g_dw2h, dw_b2, tid, pfr, bi,
             g_dw3h, g_dw3h + 256, 9 * 256);

    // layer 3: 5 phase-units (4 pairs + 1 single), K=256 in 4 chunks of 64
    float d[2][4][4];
    for (int pp = 0; pp < 5; pp++) {
        const bool single = (pp == 4);
        const int p0 = single ? 8 : 2 * pp;
        int sbst = 0;
        for (int kc = 0; kc < 4; kc++) {
            __half* w = s.wt + bi * WTBUF;
            if (kc == 0) sbst = bi;
            sts_pair(w, tid, pfr);
            bi ^= 1;
            if (kc < 3) {
                const __half* c0 = g_dw3h + p0 * 256 + (kc + 1) * 64;
                const __half* c1 = single ? c0 : g_dw3h + (p0 + 1) * 256 + (kc + 1) * 64;
                pf_pair(c0, c1, 9 * 256, tid, pfr);
            } else if (pp < 3) {
                pf_pair(g_dw3h + (2 * pp + 2) * 256, g_dw3h + (2 * pp + 3) * 256,
                        9 * 256, tid, pfr);
            } else if (pp == 3) {
                pf_pair(g_dw3h + 8 * 256, g_dw3h + 8 * 256, 9 * 256, tid, pfr);
            } else {
                pf_pair(g_pw2h, g_pw2h + 4096, 64, tid, pfr);
            }
            if (kc == 0 && tid < 128) {
                int php = tid >> 6, c = tid & 63;
                s.sbias[sbst][php][c] =
                    __ldg(dw_b3 + c * 9 + p0 + (single ? 0 : php));
            }
            __syncthreads();
            if (kc == 0) zero_d(d);
            if (!single || ph == 0)
                warp_gemm32<H2SH>(s.h2, w + ph * WTPH, d, px0, n0, lane, kc * 64);
        }

        // epilogue: pack fp16 c-pairs (+bias) into sDh[ph]
        if (!single || ph == 0) {
            #pragma unroll
            for (int mi = 0; mi < 2; mi++)
                #pragma unroll
                for (int ni = 0; ni < 4; ni++)
                    #pragma unroll
                    for (int jp = 0; jp < 2; jp++) {
                        int px = px0 + mi * 16 + (lane >> 2) + jp * 8;
                        int c  = n0 + ni * 8 + 2 * (lane & 3);
                        u32 v = ph2(d[mi][ni][jp * 2]     + s.sbias[sbst][ph][c],
                                    d[mi][ni][jp * 2 + 1] + s.sbias[sbst][ph][c + 1]);
                        *(u32*)&s.u.sDh[ph][px * SDHS + c] = v;
                    }
        }
        __syncthreads();

        // flush -> g_dwh
        const int ntask = single ? 512 : 1024;
        #pragma unroll
        for (int it = 0; it < 4; it++) {
            int idx = tid + it * NTH;
            if (idx < ntask) {
                int php = idx >> 9, rem = idx & 511;
                int px = rem >> 3, c8 = rem & 7;
                uint4 v = *(uint4*)&s.u.sDh[php][px * SDHS + c8 * 8];
                *(uint4*)&g_dwh[((pix0 + px) * 9 + p0 + php) * 64 + c8 * 8] = v;
            }
        }
        // next stage's sync orders flush reads vs sDh reuse
    }
    __syncthreads();

    // ========== tail: c-pair threads; gather + double softmax -> xc ==========
    {
        const int cp  = tid & 31;
        const int c0  = 2 * cp;
        const int pxb = tid >> 5;               // 0..7
        const float sg0 = __ldg(sigmar + c0);
        const float sg1 = __ldg(sigmar + c0 + 1);
        #pragma unroll 1
        for (int it = 0; it < 8; it++) {
            const int px  = pxb + it * 8;
            const int pix = pix0 + px;
            const int iy = s.iy[px], ix = s.ix[px];

            float dv0[9], dv1[9], h0[9], h1v[9];
            #pragma unroll
            for (int t = 0; t < 9; t++) {
                __half2 hh = *(const __half2*)&g_dwh[(pix * 9 + t) * 64 + c0];
                float2 f = __half22float2(hh);
                dv0[t] = f.x; dv1[t] = f.y;
            }
            #pragma unroll
            for (int t = 0; t < 9; t++) {
                int yy = iy + t / 3 - 1;
                int xx = ix + t % 3 - 1;
                bool ok = ((unsigned)yy < HI) && ((unsigned)xx < WI);
                if (ok) {
                    float2 hv = *(const float2*)&g_xt[(yy * WI + xx) * 64 + c0];
                    h0[t] = hv.x; h1v[t] = hv.y;
                } else { h0[t] = 0.f; h1v[t] = 0.f; }
            }
            s.xc[px * XCS + c0]     = tail1(dv0, h0,  sg0);
            s.xc[px * XCS + c0 + 1] = tail1(dv1, h1v, sg1);
        }
    }
    __syncthreads();

    // ===================== PW branch (pfr holds pw2h {0,1}) ====================
    layers12(s, pw_w1, pw_b1, g_pw2h, pw_b2, tid, pfr, bi,
             g_pw3h, g_pw3h + 256, 3 * 256);

    // layer 3: pair (0,1) + single (2); contract with xc, write out
    for (int pp = 0; pp < 2; pp++) {
        const bool single = (pp == 1);
        const int p0 = single ? 2 : 0;
        int sbst = 0;
        for (int kc = 0; kc < 4; kc++) {
            __half* w = s.wt + bi * WTBUF;
            if (kc == 0) sbst = bi;
            sts_pair(w, tid, pfr);
            bi ^= 1;
            if (kc < 3) {
                const __half* c0 = g_pw3h + p0 * 256 + (kc + 1) * 64;
                const __half* c1 = single ? c0 : g_pw3h + (p0 + 1) * 256 + (kc + 1) * 64;
                pf_pair(c0, c1, 3 * 256, tid, pfr);
            } else if (pp == 0) {
                pf_pair(g_pw3h + 2 * 256, g_pw3h + 2 * 256, 3 * 256, tid, pfr);
            }
            if (kc == 0 && tid < 128) {
                int php = tid >> 6, c = tid & 63;
                s.sbias[sbst][php][c] =
                    __ldg(pw_b3 + c * 3 + p0 + (single ? 0 : php));
            }
            __syncthreads();
            if (kc == 0) zero_d(d);
            if (!single || ph == 0)
                warp_gemm32<H2SH>(s.h2, w + ph * WTPH, d, px0, n0, lane, kc * 64);
        }

        if (!single || ph == 0) {
            #pragma unroll
            for (int mi = 0; mi < 2; mi++)
                #pragma unroll
                for (int ni = 0; ni < 4; ni++)
                    #pragma unroll
                    for (int jp = 0; jp < 2; jp++) {
                        int px = px0 + mi * 16 + (lane >> 2) + jp * 8;
                        int c  = n0 + ni * 8 + 2 * (lane & 3);
                        u32 v = ph2(d[mi][ni][jp * 2]     + s.sbias[sbst][ph][c],
                                    d[mi][ni][jp * 2 + 1] + s.sbias[sbst][ph][c + 1]);
                        *(u32*)&s.u.sDh[ph][px * SDHS + c] = v;
                    }
        }
        __syncthreads();

        // contract: out[(p0+php)][pix0+px] = sum_c xc[px][c] * sDh[php][px][c]
        const int nph = single ? 1 : 2;
        for (int php = 0; php < nph; php++) {
            const int px2 = tid >> 2;
            const int q   = tid & 3;
            const __half2* hp = (const __half2*)&s.u.sDh[php][px2 * SDHS + q * 16];
            const float*  xr = &s.xc[px2 * XCS + q * 16];
            float acc = 0.f;
            #pragma unroll
            for (int cc = 0; cc < 8; cc++) {
                float2 f = __half22float2(hp[cc]);
                acc = fmaf(f.x, xr[2 * cc],     acc);
                acc = fmaf(f.y, xr[2 * cc + 1], acc);
            }
            acc += __shfl_xor_sync(0xffffffffu, acc, 1);
            acc += __shfl_xor_sync(0xffffffffu, acc, 2);
            if (q == 0)
                out[(p0 + php) * NPIX + pix0 + px2] = acc;
        }
        // next stage's sync orders contract reads vs sDh reuse
    }
}

extern "C" void kernel_launch(void* const* d_in, const int* in_sizes, int n_in,
                              void* d_out, int out_size) {
    (void)in_sizes; (void)n_in; (void)out_size;
    const float* x      = (const float*)d_in[0];
    const float* pose   = (const float*)d_in[1];
    const int*   imY    = (const int*)  d_in[2];
    const int*   imX    = (const int*)  d_in[3];
    const float* sigmar = (const float*)d_in[4];
    const float* dw_w1  = (const float*)d_in[5];
    const float* dw_b1  = (const float*)d_in[6];
    const float* dw_w2  = (const float*)d_in[7];
    const float* dw_b2  = (const float*)d_in[8];
    const float* dw_w3  = (const float*)d_in[9];
    const float* dw_b3  = (const float*)d_in[10];
    const float* pw_w1  = (const float*)d_in[11];
    const float* pw_b1  = (const float*)d_in[12];
    const float* pw_w2  = (const float*)d_in[13];
    const float* pw_b2  = (const float*)d_in[14];
    const float* pw_w3  = (const float*)d_in[15];
    const float* pw_b3  = (const float*)d_in[16];
    float* out = (float*)d_out;

    const int tsmem = 64 * 257 * 4;
    cudaFuncSetAttribute(prep_kernel,
                         cudaFuncAttributeMaxDynamicSharedMemorySize, tsmem);
    prep_kernel<<<256, 256, tsmem>>>(x, dw_w2, dw_w3, pw_w2, pw_w3);

    const int asmem = (int)sizeof(SmemA);
    cudaFuncSetAttribute(biup_fused,
                         cudaFuncAttributeMaxDynamicSharedMemorySize, asmem);
    biup_fused<<<NPIX / PPB, NTH, asmem>>>(
        pose, imY, imX, sigmar,
        dw_w1, dw_b1, dw_b2, dw_b3,
        pw_w1, pw_b1, pw_b2, pw_b3,
        out);
}

// round 17
// speedup vs baseline: 2.3333x; 1.0132x over previous
#include <cuda_runtime.h>
#include <cuda_fp16.h>
#include <math.h>

#define HI    256
#define WI    256
#define NPIX  262144
#define PPB   64
#define NTH   256

#define H2SH  264     // h2 fp16 stride (528B): 16B-unit stride %32 = 4 -> conflict-free
#define H1SH  72      // h1 fp16 stride
#define WT2S  72      // weight tile stride (64k + pad)
#define WTPH  (64 * WT2S)     // one phase tile: 4608 halfs (9216 B)
#define WTBUF (2 * WTPH)      // one buffer (2 phases)
#define SDHS  72      // sDh fp16 stride
#define XCS   65      // xc f32 stride

typedef unsigned int u32;

__device__ float  g_xt[HI * WI * 64];     // x transposed [y][x][c]
__device__ __half g_dwh[NPIX * 9 * 64];   // dw scratch fp16 [pix][t][c]
__device__ __half g_dw2h[256 * 64];
__device__ __half g_dw3h[576 * 256];
__device__ __half g_pw2h[256 * 64];
__device__ __half g_pw3h[192 * 256];

struct __align__(16) SmemA {
    __half h2[PPB * H2SH];                     // 33792 B
    __half wt[2 * WTBUF];                      // 36864 B (2 buffers x 2 phases)
    union { __half h1[PPB * H1SH]; __half sDh[2][PPB * SDHS]; } u;  // 18432 B
    float xc[PPB * XCS];                       // 16640 B
    float pose[3][PPB];                        //   768 B
    int   iy[PPB];                             //   256 B
    int   ix[PPB];                             //   256 B
    float sbias[2][2][64];                     //  1024 B
};                                             // ~105.5 KB -> 2 blocks/SM

static __device__ __forceinline__ u32 ph2(float a, float b) {
    __half2 h = __floats2half2_rn(a, b);
    return *reinterpret_cast<u32*>(&h);
}

static __device__ __forceinline__ void mma_f16(float d[4], const u32 a[4], u32 b0, u32 b1) {
    asm volatile(
        "mma.sync.aligned.m16n8k16.row.col.f32.f16.f16.f32 "
        "{%0,%1,%2,%3}, {%4,%5,%6,%7}, {%8,%9}, {%0,%1,%2,%3};"
        : "+f"(d[0]), "+f"(d[1]), "+f"(d[2]), "+f"(d[3])
        : "r"(a[0]), "r"(a[1]), "r"(a[2]), "r"(a[3]), "r"(b0), "r"(b1));
}

#define LDSM4(r, addr) \
    asm volatile("ldmatrix.sync.aligned.m8n8.x4.shared.b16 {%0,%1,%2,%3}, [%4];" \
                 : "=r"((r)[0]), "=r"((r)[1]), "=r"((r)[2]), "=r"((r)[3]) : "r"(addr))

#define CA_COMMIT() asm volatile("cp.async.commit_group;" ::: "memory")
#define CA_WAIT0()  asm volatile("cp.async.wait_group 0;" ::: "memory")

static __device__ __forceinline__ u32 smem_u32(const void* p) {
    return (u32)__cvta_generic_to_shared(p);
}

// ======== prep: transpose x AND convert weights (single launch) ========
__global__ void __launch_bounds__(256)
prep_kernel(const float* __restrict__ x,
            const float* __restrict__ dw2, const float* __restrict__ dw3,
            const float* __restrict__ pw2, const float* __restrict__ pw3) {
    extern __shared__ float tile[];   // [64][257]
    const int y   = blockIdx.x;
    const int tid = threadIdx.x;
    for (int i = tid; i < 64 * 256; i += 256) {
        int c = i >> 8, xx = i & 255;
        tile[c * 257 + xx] = __ldg(x + c * 65536 + y * 256 + xx);
    }
    __syncthreads();
    for (int i = tid; i < 64 * 256; i += 256) {
        int xx = i >> 6, c = i & 63;
        g_xt[(y * 256 + xx) * 64 + c] = tile[c * 257 + xx];
    }
    int i0 = blockIdx.x * 256 + tid;
    int n  = gridDim.x * 256;
    for (int k = i0; k < 256 * 64; k += n) g_dw2h[k] = __float2half_rn(__ldg(dw2 + k));
    for (int k = i0; k < 576 * 256; k += n) g_dw3h[k] = __float2half_rn(__ldg(dw3 + k));
    for (int k = i0; k < 256 * 64; k += n) g_pw2h[k] = __float2half_rn(__ldg(pw2 + k));
    for (int k = i0; k < 192 * 256; k += n) g_pw3h[k] = __float2half_rn(__ldg(pw3 + k));
}

// ======== cp.async staging of a chunk pair (two 64n x 64k fp16 chunks) ========
static __device__ __forceinline__ void ca_pair(__half* __restrict__ dst,
                                               const __half* __restrict__ s0,
                                               const __half* __restrict__ s1,
                                               int rs, int tid) {
    #pragma unroll
    for (int it = 0; it < 2; it++) {
        int idx = tid + it * NTH;
        int row = idx >> 3, k8 = idx & 7;
        u32 d0 = smem_u32(&dst[row * WT2S + k8 * 8]);
        asm volatile("cp.async.cg.shared.global [%0], [%1], 16;"
                     :: "r"(d0), "l"(s0 + row * rs + k8 * 8) : "memory");
        u32 d1 = smem_u32(&dst[WTPH + row * WT2S + k8 * 8]);
        asm volatile("cp.async.cg.shared.global [%0], [%1], 16;"
                     :: "r"(d1), "l"(s1 + row * rs + k8 * 8) : "memory");
    }
}

// ======== warp GEMM: 32px x 32n, K=64 (ldmatrix + 4x m16n8k16 per ks) ========
template<int ASH>
static __device__ __forceinline__ void warp_gemm32(const __half* __restrict__ A,
                                                   const __half* __restrict__ W,
                                                   float d[2][4][4],
                                                   int px0, int n0, int lane, int acol0)
{
    const int g = lane >> 3, r = lane & 7;
    u32 a0 = smem_u32(A + (px0 + (g & 1) * 8 + r) * ASH + acol0 + (g >> 1) * 8);
    u32 a1 = a0 + 16 * ASH * 2;          // mi = 1 (+16 px rows)
    u32 b0 = smem_u32(W + (n0 + g * 8 + r) * WT2S);
    u32 b1 = b0 + 16;                    // k + 8
    #pragma unroll
    for (int ks = 0; ks < 4; ks++) {
        u32 a[2][4], t0[4], t1[4];
        LDSM4(a[0], a0);
        LDSM4(a[1], a1);
        LDSM4(t0, b0);                   // t0[ni] = b[ni] frag for k0-7
        LDSM4(t1, b1);                   // t1[ni] = b[ni] frag for k8-15
        #pragma unroll
        for (int mi = 0; mi < 2; mi++)
            #pragma unroll
            for (int ni = 0; ni < 4; ni++)
                mma_f16(d[mi][ni], a[mi], t0[ni], t1[ni]);
        a0 += 32; a1 += 32; b0 += 32; b1 += 32;
    }
}

static __device__ __forceinline__ void zero_d(float d[2][4][4]) {
    #pragma unroll
    for (int mi = 0; mi < 2; mi++)
        #pragma unroll
        for (int ni = 0; ni < 4; ni++)
            #pragma unroll
            for (int j = 0; j < 4; j++) d[mi][ni][j] = 0.f;
}

// ======== layers 1+2 of one branch ========
// Entry: async group targeting buf bi (w2h och{0,1}) outstanding.
// Exit:  async group targeting buf bi (next branch chunk pair) outstanding.
static __device__ void layers12(SmemA& s,
                                const float* __restrict__ w1, const float* __restrict__ b1,
                                const __half* __restrict__ w2h, const float* __restrict__ b2,
                                int tid, int& bi,
                                const __half* __restrict__ nb0,
                                const __half* __restrict__ nb1, int nrs)
{
    const int warp = tid >> 5, lane = tid & 31;
    const int ph  = warp & 1;
    const int px0 = ((warp >> 1) & 1) * 32;
    const int n0  = (warp >> 2) * 32;

    // preload both layer-2 bias pairs (visible after first stage sync)
    {
        int op = tid >> 7, phh = (tid >> 6) & 1, c = tid & 63;
        s.sbias[op][phh][c] = __ldg(b2 + (op * 2 + phh) * 64 + c);
    }

    // layer 1 (scalar) -> h1 fp16
    {
        int o = tid & 63, pb = tid >> 6;       // 4 groups of 16 px
        float wa = __ldg(w1 + o * 3 + 0);
        float wb = __ldg(w1 + o * 3 + 1);
        float wc = __ldg(w1 + o * 3 + 2);
        float bb = __ldg(b1 + o);
        #pragma unroll 4
        for (int p = pb * 16; p < pb * 16 + 16; p++) {
            float v = fmaf(wa, s.pose[0][p],
                      fmaf(wb, s.pose[1][p],
                      fmaf(wc, s.pose[2][p], bb)));
            s.u.h1[p * H1SH + o] = __float2half_rn(fmaxf(v, 0.f));
        }
    }

    // layer 2: 2 och-pair stages, K=64 (phase ph handles och = op*2+ph)
    for (int op = 0; op < 2; op++) {
        CA_WAIT0();
        __syncthreads();
        if (op == 0) ca_pair(s.wt + (bi ^ 1) * WTBUF, w2h + 2 * 4096, w2h + 3 * 4096, 64, tid);
        else         ca_pair(s.wt + (bi ^ 1) * WTBUF, nb0, nb1, nrs, tid);
        CA_COMMIT();

        float d[2][4][4];
        zero_d(d);
        warp_gemm32<H1SH>(s.u.h1, s.wt + bi * WTBUF + ph * WTPH, d, px0, n0, lane, 0);

        const int och = op * 2 + ph;
        #pragma unroll
        for (int mi = 0; mi < 2; mi++)
            #pragma unroll
            for (int ni = 0; ni < 4; ni++) {
                int px  = px0 + mi * 16 + (lane >> 2);
                int olb = n0 + ni * 8 + 2 * (lane & 3);
                float b0v = s.sbias[op][ph][olb], b1v = s.sbias[op][ph][olb + 1];
                u32 v01 = ph2(fmaxf(d[mi][ni][0] + b0v, 0.f),
                              fmaxf(d[mi][ni][1] + b1v, 0.f));
                *(u32*)&s.h2[px * H2SH + och * 64 + olb] = v01;
                u32 v23 = ph2(fmaxf(d[mi][ni][2] + b0v, 0.f),
                              fmaxf(d[mi][ni][3] + b1v, 0.f));
                *(u32*)&s.h2[(px + 8) * H2SH + och * 64 + olb] = v23;
            }
        bi ^= 1;
    }
}

// ======== per-channel double-softmax tail ========
static __device__ __forceinline__ float tail1(const float* dwv, const float* h, float sg) {
    float m = dwv[0];
    #pragma unroll
    for (int t = 1; t < 9; t++) m = fmaxf(m, dwv[t]);
    float es = 0.f, hm = 0.f;
    #pragma unroll
    for (int t = 0; t < 9; t++) {
        float e = __expf(dwv[t] - m);
        es += e;
        hm  = fmaf(h[t], e, hm);
    }
    float mean = hm / es;
    float bw[9], m2 = -3.4e38f;
    #pragma unroll
    for (int t = 0; t < 9; t++) {
        float dd = h[t] - mean;
        bw[t] = fmaf(sg * dd, dd, dwv[t]);
        m2 = fmaxf(m2, bw[t]);
    }
    float s2 = 0.f, xcv = 0.f;
    #pragma unroll
    for (int t = 0; t < 9; t++) {
        float ee = __expf(bw[t] - m2);
        s2  += ee;
        xcv  = fmaf(h[t], ee, xcv);
    }
    return xcv / s2;
}

__global__ void __launch_bounds__(NTH, 2)
biup_fused(const float* __restrict__ poseMap,
           const int*   __restrict__ imY, const int* __restrict__ imX,
           const float* __restrict__ sigmar,
           const float* __restrict__ dw_w1, const float* __restrict__ dw_b1,
           const float* __restrict__ dw_b2, const float* __restrict__ dw_b3,
           const float* __restrict__ pw_w1, const float* __restrict__ pw_b1,
           const float* __restrict__ pw_b2, const float* __restrict__ pw_b3,
           float* __restrict__ out)
{
    extern __shared__ __align__(16) unsigned char smem_raw[];
    SmemA& s = *reinterpret_cast<SmemA*>(smem_raw);
    const int tid  = threadIdx.x;
    const int warp = tid >> 5, lane = tid & 31;
    const int ph  = warp & 1;
    const int px0 = ((warp >> 1) & 1) * 32;
    const int n0  = (warp >> 2) * 32;
    const int pix0 = blockIdx.x * PPB;

    // chain head: dw2 och {0,1} -> buf 0
    ca_pair(s.wt, g_dw2h, g_dw2h + 4096, 64, tid);
    CA_COMMIT();
    int bi = 0;

    if (tid < 3 * PPB) {
        int j = tid >> 6, pp = tid & 63;
        s.pose[j][pp] = __ldg(poseMap + j * NPIX + pix0 + pp);
    }
    if (tid < PPB)           s.iy[tid]       = __ldg(imY + pix0 + tid);
    else if (tid < 2 * PPB)  s.ix[tid - PPB] = __ldg(imX + pix0 + tid - PPB);
    __syncthreads();

    // ===================== DW branch =====================
    layers12(s, dw_w1, dw_b1, g_dw2h, dw_b2, tid, bi,
             g_dw3h, g_dw3h + 256, 9 * 256);

    // layer 3: 5 phase-units (4 pairs + 1 single), K=256 in 4 chunks of 64
    float d[2][4][4];
    for (int pp = 0; pp < 5; pp++) {
        const bool single = (pp == 4);
        const int p0 = single ? 8 : 2 * pp;
        const int sbslot = pp & 1;
        for (int kc = 0; kc < 4; kc++) {
            CA_WAIT0();
            __syncthreads();
            // issue next chunk pair -> buf bi^1
            if (kc < 3) {
                const __half* c0 = g_dw3h + p0 * 256 + (kc + 1) * 64;
                const __half* c1 = single ? c0 : g_dw3h + (p0 + 1) * 256 + (kc + 1) * 64;
                ca_pair(s.wt + (bi ^ 1) * WTBUF, c0, c1, 9 * 256, tid);
            } else if (pp < 3) {
                ca_pair(s.wt + (bi ^ 1) * WTBUF,
                        g_dw3h + (2 * pp + 2) * 256, g_dw3h + (2 * pp + 3) * 256,
                        9 * 256, tid);
            } else if (pp == 3) {
                ca_pair(s.wt + (bi ^ 1) * WTBUF,
                        g_dw3h + 8 * 256, g_dw3h + 8 * 256, 9 * 256, tid);
            } else {
                ca_pair(s.wt + (bi ^ 1) * WTBUF, g_pw2h, g_pw2h + 4096, 64, tid);
            }
            CA_COMMIT();
            if (kc == 0 && tid < 128) {
                int php = tid >> 6, c = tid & 63;
                s.sbias[sbslot][php][c] = __ldg(dw_b3 + c * 9 + p0 + (single ? 0 : php));
            }
            if (kc == 0) zero_d(d);
            if (!single || ph == 0)
                warp_gemm32<H2SH>(s.h2, s.wt + bi * WTBUF + ph * WTPH, d, px0, n0, lane, kc * 64);
            bi ^= 1;
        }

        // epilogue: pack fp16 c-pairs (+bias) into sDh[ph]
        if (!single || ph == 0) {
            #pragma unroll
            for (int mi = 0; mi < 2; mi++)
                #pragma unroll
                for (int ni = 0; ni < 4; ni++)
                    #pragma unroll
                    for (int jp = 0; jp < 2; jp++) {
                        int px = px0 + mi * 16 + (lane >> 2) + jp * 8;
                        int c  = n0 + ni * 8 + 2 * (lane & 3);
                        u32 v = ph2(d[mi][ni][jp * 2]     + s.sbias[sbslot][ph][c],
                                    d[mi][ni][jp * 2 + 1] + s.sbias[sbslot][ph][c + 1]);
                        *(u32*)&s.u.sDh[ph][px * SDHS + c] = v;
                    }
        }
        __syncthreads();

        // flush -> g_dwh
        const int ntask = single ? 512 : 1024;
        #pragma unroll
        for (int it = 0; it < 4; it++) {
            int idx = tid + it * NTH;
            if (idx < ntask) {
                int php = idx >> 9, rem = idx & 511;
                int px = rem >> 3, c8 = rem & 7;
                uint4 v = *(uint4*)&s.u.sDh[php][px * SDHS + c8 * 8];
                *(uint4*)&g_dwh[((pix0 + px) * 9 + p0 + php) * 64 + c8 * 8] = v;
            }
        }
        // next stage's sync orders flush reads vs sDh reuse
    }
    __syncthreads();

    // ========== tail: c-pair threads; gather + double softmax -> xc ==========
    {
        const int cp  = tid & 31;
        const int c0  = 2 * cp;
        const int pxb = tid >> 5;               // 0..7
        const float sg0 = __ldg(sigmar + c0);
        const float sg1 = __ldg(sigmar + c0 + 1);
        #pragma unroll 1
        for (int it = 0; it < 8; it++) {
            const int px  = pxb + it * 8;
            const int pix = pix0 + px;
            const int iy = s.iy[px], ix = s.ix[px];

            float dv0[9], dv1[9], h0[9], h1v[9];
            #pragma unroll
            for (int t = 0; t < 9; t++) {
                __half2 hh = *(const __half2*)&g_dwh[(pix * 9 + t) * 64 + c0];
                float2 f = __half22float2(hh);
                dv0[t] = f.x; dv1[t] = f.y;
            }
            #pragma unroll
            for (int t = 0; t < 9; t++) {
                int yy = iy + t / 3 - 1;
                int xx = ix + t % 3 - 1;
                bool ok = ((unsigned)yy < HI) && ((unsigned)xx < WI);
                if (ok) {
                    float2 hv = *(const float2*)&g_xt[(yy * WI + xx) * 64 + c0];
                    h0[t] = hv.x; h1v[t] = hv.y;
                } else { h0[t] = 0.f; h1v[t] = 0.f; }
            }
            s.xc[px * XCS + c0]     = tail1(dv0, h0,  sg0);
            s.xc[px * XCS + c0 + 1] = tail1(dv1, h1v, sg1);
        }
    }
    __syncthreads();

    // ===================== PW branch (group for pw2h {0,1} outstanding) ========
    layers12(s, pw_w1, pw_b1, g_pw2h, pw_b2, tid, bi,
             g_pw3h, g_pw3h + 256, 3 * 256);

    // layer 3: pair (0,1) + single (2); contract with xc, write out
    for (int pp = 0; pp < 2; pp++) {
        const bool single = (pp == 1);
        const int p0 = single ? 2 : 0;
        const int sbslot = pp & 1;
        for (int kc = 0; kc < 4; kc++) {
            CA_WAIT0();
            __syncthreads();
            if (kc < 3) {
                const __half* c0 = g_pw3h + p0 * 256 + (kc + 1) * 64;
                const __half* c1 = single ? c0 : g_pw3h + (p0 + 1) * 256 + (kc + 1) * 64;
                ca_pair(s.wt + (bi ^ 1) * WTBUF, c0, c1, 3 * 256, tid);
                CA_COMMIT();
            } else if (pp == 0) {
                ca_pair(s.wt + (bi ^ 1) * WTBUF,
                        g_pw3h + 2 * 256, g_pw3h + 2 * 256, 3 * 256, tid);
                CA_COMMIT();
            }
            if (kc == 0 && tid < 128) {
                int php = tid >> 6, c = tid & 63;
                s.sbias[sbslot][php][c] = __ldg(pw_b3 + c * 3 + p0 + (single ? 0 : php));
            }
            if (kc == 0) zero_d(d);
            if (!single || ph == 0)
                warp_gemm32<H2SH>(s.h2, s.wt + bi * WTBUF + ph * WTPH, d, px0, n0, lane, kc * 64);
            bi ^= 1;
        }

        if (!single || ph == 0) {
            #pragma unroll
            for (int mi = 0; mi < 2; mi++)
                #pragma unroll
                for (int ni = 0; ni < 4; ni++)
                    #pragma unroll
                    for (int jp = 0; jp < 2; jp++) {
                        int px = px0 + mi * 16 + (lane >> 2) + jp * 8;
                        int c  = n0 + ni * 8 + 2 * (lane & 3);
                        u32 v = ph2(d[mi][ni][jp * 2]     + s.sbias[sbslot][ph][c],
                                    d[mi][ni][jp * 2 + 1] + s.sbias[sbslot][ph][c + 1]);
                        *(u32*)&s.u.sDh[ph][px * SDHS + c] = v;
                    }
        }
        __syncthreads();

        // contract: out[(p0+php)][pix0+px] = sum_c xc[px][c] * sDh[php][px][c]
        const int nph = single ? 1 : 2;
        for (int php = 0; php < nph; php++) {
            const int px2 = tid >> 2;
            const int q   = tid & 3;
            const __half2* hp = (const __half2*)&s.u.sDh[php][px2 * SDHS + q * 16];
            const float*  xr = &s.xc[px2 * XCS + q * 16];
            float acc = 0.f;
            #pragma unroll
            for (int cc = 0; cc < 8; cc++) {
                float2 f = __half22float2(hp[cc]);
                acc = fmaf(f.x, xr[2 * cc],     acc);
                acc = fmaf(f.y, xr[2 * cc + 1], acc);
            }
            acc += __shfl_xor_sync(0xffffffffu, acc, 1);
            acc += __shfl_xor_sync(0xffffffffu, acc, 2);
            if (q == 0)
                out[(p0 + php) * NPIX + pix0 + px2] = acc;
        }
        // next stage's sync orders contract reads vs sDh reuse
    }
}

extern "C" void kernel_launch(void* const* d_in, const int* in_sizes, int n_in,
                              void* d_out, int out_size) {
    (void)in_sizes; (void)n_in; (void)out_size;
    const float* x      = (const float*)d_in[0];
    const float* pose   = (const float*)d_in[1];
    const int*   imY    = (const int*)  d_in[2];
    const int*   imX    = (const int*)  d_in[3];
    const float* sigmar = (const float*)d_in[4];
    const float* dw_w1  = (const float*)d_in[5];
    const float* dw_b1  = (const float*)d_in[6];
    const float* dw_w2  = (const float*)d_in[7];
    const float* dw_b2  = (const float*)d_in[8];
    const float* dw_w3  = (const float*)d_in[9];
    const float* dw_b3  = (const float*)d_in[10];
    const float* pw_w1  = (const float*)d_in[11];
    const float* pw_b1  = (const float*)d_in[12];
    const float* pw_w2  = (const float*)d_in[13];
    const float* pw_b2  = (const float*)d_in[14];
    const float* pw_w3  = (const float*)d_in[15];
    const float* pw_b3  = (const float*)d_in[16];
    float* out = (float*)d_out;

    const int tsmem = 64 * 257 * 4;
    cudaFuncSetAttribute(prep_kernel,
                         cudaFuncAttributeMaxDynamicSharedMemorySize, tsmem);
    prep_kernel<<<256, 256, tsmem>>>(x, dw_w2, dw_w3, pw_w2, pw_w3);

    const int asmem = (int)sizeof(SmemA);
    cudaFuncSetAttribute(biup_fused,
                         cudaFuncAttributeMaxDynamicSharedMemorySize, asmem);
    biup_fused<<<NPIX / PPB, NTH, asmem>>>(
        pose, imY, imX, sigmar,
        dw_w1, dw_b1, dw_b2, dw_b3,
        pw_w1, pw_b1, pw_b2, pw_b3,
        out);
}